// round 4
// baseline (speedup 1.0000x reference)
#include <cuda_runtime.h>
#include <math.h>

#define NBATCH 64
#define NPTSB  1024
#define NP     65536
#define KNN    16
#define FINF   3.402823466e38f

// ---------------- scratch (static __device__, no allocs) ----------------
__device__ int   g_idx[NP * KNN];              // knn indices (within batch)
__device__ float g_feat[NP * 192];             // [x1 | x2 | x3] concat, stride 192
__device__ float g_A[NP * 64];                 // point-level A = X@(W1a-W1b)+b1
__device__ float g_P[NP * 64];                 // point-level P = X@W1b
__device__ float g_h1[NP * 128];
__device__ float g_h2[NP * 64];
__device__ float g_h3[NP * 32];

__device__ __forceinline__ float* buf_sel(int s) {
  switch (s) {
    case 0: return g_feat;
    case 1: return g_h1;
    case 2: return g_h2;
    case 3: return g_h3;
  }
  return 0;
}

// ---------------- fused KNN, d_in = 1 ----------------
// score(i,j) = xj^2 - 2 xi xj  (row-constant |xi|^2 dropped; ordering preserved)
__global__ __launch_bounds__(256) void knn1_kernel(const float* __restrict__ x) {
  int gw = (blockIdx.x << 3) + (threadIdx.x >> 5);   // row 0..65535
  int lane = threadIdx.x & 31;
  int b = gw >> 10;
  float xi = x[gw];
  const float* xb = x + (b << 10);
  float v[32];
#pragma unroll
  for (int q = 0; q < 32; q++) {
    float xj = xb[(q << 5) + lane];
    v[q] = xj * (xj - 2.0f * xi);
  }
  float bv = v[0]; int bq = 0;
#pragma unroll
  for (int q = 1; q < 32; q++) if (v[q] < bv) { bv = v[q]; bq = q; }
  int bidx = (bq << 5) + lane;
#pragma unroll 1
  for (int it = 0; it < 16; it++) {
    float wv = bv; int wi = bidx;
#pragma unroll
    for (int o = 16; o; o >>= 1) {
      float ov = __shfl_down_sync(0xffffffffu, wv, o);
      int   oi = __shfl_down_sync(0xffffffffu, wi, o);
      if (ov < wv || (ov == wv && oi < wi)) { wv = ov; wi = oi; }
    }
    wi = __shfl_sync(0xffffffffu, wi, 0);
    if (lane == 0) g_idx[(gw << 4) + it] = wi;
    if ((wi & 31) == lane) {
      int qr = wi >> 5;
#pragma unroll
      for (int q = 0; q < 32; q++) if (q == qr) v[q] = FINF;
      bv = v[0]; bq = 0;
#pragma unroll
      for (int q = 1; q < 32; q++) if (v[q] < bv) { bv = v[q]; bq = q; }
      bidx = (bq << 5) + lane;
    }
  }
}

// ---------------- fused KNN, d_in = 64 ----------------
// Block: 256 threads, 64-row stripe vs all 1024 cols in 128-col chunks.
// GEMM micro: 4 rows x 8 cols, conflict-free split mapping.
// Scores staged transposed in smem; 64 threads keep per-row top-16.
__device__ __forceinline__ void tk_insert(float v, int j, float* best, int* bidx,
                                          float& thr) {
  int p = 15;
  while (p > 0 && best[p - 1] > v) {
    best[p] = best[p - 1]; bidx[p] = bidx[p - 1]; p--;
  }
  best[p] = v; bidx[p] = j;
  thr = best[15];
}

__global__ __launch_bounds__(256) void knn64_kernel(int featOff) {
  extern __shared__ float sm[];
  float* xiT = sm;                         // [64][68]  k-major, 64 rows
  float* xjT = sm + 64 * 68;               // [64][132] k-major, 128 cols
  float* sT  = sm + 64 * 68 + 64 * 132;    // [128][68] col-major scores
  float* sqj = sT + 128 * 68;              // [128]

  int tid = threadIdx.x;
  int b = blockIdx.x >> 4;
  int i0 = (blockIdx.x & 15) << 6;
  const float* Xb = g_feat + (((size_t)b << 10)) * 192 + featOff;

  // load xiT (64 rows x 64 k, transposed)
  for (int t = tid; t < 1024; t += 256) {
    int r = t >> 4, kg = (t & 15) << 2;
    float4 v = *(const float4*)&Xb[(size_t)(i0 + r) * 192 + kg];
    xiT[(kg + 0) * 68 + r] = v.x; xiT[(kg + 1) * 68 + r] = v.y;
    xiT[(kg + 2) * 68 + r] = v.z; xiT[(kg + 3) * 68 + r] = v.w;
  }

  float best[16]; int bidx[16];
#pragma unroll
  for (int q = 0; q < 16; q++) { best[q] = FINF; bidx[q] = 0; }
  float thr = FINF;

  int rb = tid & 15, cb = tid >> 4;
  int r0 = rb << 2;
  int c0 = cb << 2;

  for (int chunk = 0; chunk < 8; chunk++) {
    int j0 = chunk << 7;
    __syncthreads();   // scores/xjT free
    // load xjT: 128 cols x 64 k transposed
    for (int t = tid; t < 2048; t += 256) {
      int r = t >> 4, kg = (t & 15) << 2;
      float4 v = *(const float4*)&Xb[(size_t)(j0 + r) * 192 + kg];
      xjT[(kg + 0) * 132 + r] = v.x; xjT[(kg + 1) * 132 + r] = v.y;
      xjT[(kg + 2) * 132 + r] = v.z; xjT[(kg + 3) * 132 + r] = v.w;
    }
    __syncthreads();   // xjT ready
    if (tid < 128) {
      float sq = 0.f;
#pragma unroll
      for (int k = 0; k < 64; k++) { float u = xjT[k * 132 + tid]; sq += u * u; }
      sqj[tid] = sq;
    }
    // GEMM 64x128, K=64
    float acc[4][8];
#pragma unroll
    for (int i = 0; i < 4; i++)
#pragma unroll
      for (int j = 0; j < 8; j++) acc[i][j] = 0.f;
#pragma unroll
    for (int k = 0; k < 64; k++) {
      float a[4], bv[8];
      *(float4*)&a[0]  = *(const float4*)&xiT[k * 68 + r0];
      *(float4*)&bv[0] = *(const float4*)&xjT[k * 132 + c0];
      *(float4*)&bv[4] = *(const float4*)&xjT[k * 132 + 64 + c0];
#pragma unroll
      for (int i = 0; i < 4; i++)
#pragma unroll
        for (int j = 0; j < 8; j++) acc[i][j] += a[i] * bv[j];
    }
    __syncthreads();   // sqj ready
    // write scores transposed: sT[c][r] = sqj[c] - 2*dot
#pragma unroll
    for (int j = 0; j < 8; j++) {
      int c = (j < 4) ? (c0 + j) : (64 + c0 + j - 4);
      float sq = sqj[c];
      float4 v;
      v.x = sq - 2.f * acc[0][j];
      v.y = sq - 2.f * acc[1][j];
      v.z = sq - 2.f * acc[2][j];
      v.w = sq - 2.f * acc[3][j];
      *(float4*)&sT[c * 68 + r0] = v;
    }
    __syncthreads();   // scores ready
    if (tid < 64) {
#pragma unroll 4
      for (int c = 0; c < 128; c++) {
        float v = sT[c * 68 + tid];
        if (v < thr) tk_insert(v, j0 + c, best, bidx, thr);
      }
    }
  }
  if (tid < 64) {
    int gi = (b << 10) + i0 + tid;
#pragma unroll
    for (int q = 0; q < 16; q++) g_idx[(gi << 4) + q] = bidx[q];
  }
}

// ---------------- point-level A/P precompute ----------------
__global__ __launch_bounds__(256) void prec1_kernel(const float* __restrict__ x,
                                                    const float* __restrict__ w1,
                                                    const float* __restrict__ b1) {
  int t = blockIdx.x * 256 + threadIdx.x;
  int i = t >> 4;
  int c = (t & 15) << 2;
  float xi = x[i];
  float4 wa = *(const float4*)&w1[c];
  float4 wb = *(const float4*)&w1[64 + c];
  float4 bb = *(const float4*)&b1[c];
  float4 A, P;
  A.x = xi * (wa.x - wb.x) + bb.x;  P.x = xi * wb.x;
  A.y = xi * (wa.y - wb.y) + bb.y;  P.y = xi * wb.y;
  A.z = xi * (wa.z - wb.z) + bb.z;  P.z = xi * wb.z;
  A.w = xi * (wa.w - wb.w) + bb.w;  P.w = xi * wb.w;
  *(float4*)&g_A[(size_t)i * 64 + c] = A;
  *(float4*)&g_P[(size_t)i * 64 + c] = P;
}

__global__ __launch_bounds__(256) void prec64_kernel(int featOff,
                                                     const float* __restrict__ w1,
                                                     const float* __restrict__ b1) {
  __shared__ float xs[64][36];
  __shared__ float wd[32][64];
  __shared__ float wb[32][64];
  int tid = threadIdx.x;
  int row0 = blockIdx.x * 64;
  int rb = tid & 15, cb = tid >> 4;
  int r0 = rb * 4, c0 = cb * 4;
  float accA[4][4] = {}, accP[4][4] = {};

  for (int kc = 0; kc < 64; kc += 32) {
    __syncthreads();
    for (int t = tid; t < 2048; t += 256) {
      int rr = t >> 5, dd = t & 31;
      xs[rr][dd] = g_feat[(size_t)(row0 + rr) * 192 + featOff + kc + dd];
    }
    for (int t = tid; t < 2048; t += 256) {
      int kk = t >> 6, cc = t & 63;
      float bw = w1[(size_t)(64 + kc + kk) * 64 + cc];
      wb[kk][cc] = bw;
      wd[kk][cc] = w1[(size_t)(kc + kk) * 64 + cc] - bw;
    }
    __syncthreads();
#pragma unroll
    for (int k = 0; k < 32; k += 4) {
      float a[4][4];
#pragma unroll
      for (int i = 0; i < 4; i++) {
        float4 v = *(const float4*)&xs[r0 + i][k];
        a[i][0] = v.x; a[i][1] = v.y; a[i][2] = v.z; a[i][3] = v.w;
      }
#pragma unroll
      for (int kk = 0; kk < 4; kk++)
#pragma unroll
        for (int cc = 0; cc < 4; cc++) {
          float wdv = wd[k + kk][c0 + cc];
          float wbv = wb[k + kk][c0 + cc];
#pragma unroll
          for (int i = 0; i < 4; i++) {
            accA[i][cc] += a[i][kk] * wdv;
            accP[i][cc] += a[i][kk] * wbv;
          }
        }
    }
  }
#pragma unroll
  for (int i = 0; i < 4; i++)
#pragma unroll
    for (int cc = 0; cc < 4; cc++) {
      int r = row0 + r0 + i, c = c0 + cc;
      g_A[(size_t)r * 64 + c] = accA[i][cc] + b1[c];
      g_P[(size_t)r * 64 + c] = accP[i][cc];
    }
}

// ---------------- fused edge kernel ----------------
// 8 points x 16 edges = 128 h1 rows, 128x64 GEMM, 8x8 split micro, seg-max.
__global__ __launch_bounds__(128, 4) void edge_kernel(const float* __restrict__ w2,
                                                      const float* __restrict__ b2,
                                                      int outOff) {
  __shared__ float h1T[64][132];
  __shared__ float w2s[32][68];   // reused as red[32][68] after GEMM
  int tid = threadIdx.x;
  int p0 = blockIdx.x << 3;

  // build h1 rows transposed: h1T[d][r] = relu(A[i(r)][d] + P[j(r)][d])
  {
    int r = tid;
    int p = r >> 4, e = r & 15;
    int gi = p0 + p;
    int bb = gi >> 10;
    int j = g_idx[(gi << 4) + e];
    const float* Ar = g_A + ((size_t)gi << 6);
    const float* Pr = g_P + ((size_t)((bb << 10) + j) << 6);
#pragma unroll
    for (int d = 0; d < 64; d += 4) {
      float4 av = *(const float4*)(Ar + d);
      float4 pv = *(const float4*)(Pr + d);
      h1T[d + 0][r] = fmaxf(av.x + pv.x, 0.f);
      h1T[d + 1][r] = fmaxf(av.y + pv.y, 0.f);
      h1T[d + 2][r] = fmaxf(av.z + pv.z, 0.f);
      h1T[d + 3][r] = fmaxf(av.w + pv.w, 0.f);
    }
  }

  int rb = tid & 15, cb = tid >> 4;   // cb 0..7
  int r0 = rb << 2, c0 = cb << 2;
  float acc[8][8];
#pragma unroll
  for (int i = 0; i < 8; i++)
#pragma unroll
    for (int j = 0; j < 8; j++) acc[i][j] = 0.f;

  for (int kc = 0; kc < 64; kc += 32) {
    __syncthreads();
    for (int t = tid; t < 512; t += 128) {
      int k = t >> 4, cg = (t & 15) << 2;
      *(float4*)&w2s[k][cg] = *(const float4*)&w2[((size_t)(kc + k) << 6) + cg];
    }
    __syncthreads();
#pragma unroll
    for (int k = 0; k < 32; k++) {
      float a[8], bv[8];
      *(float4*)&a[0]  = *(const float4*)&h1T[kc + k][r0];
      *(float4*)&a[4]  = *(const float4*)&h1T[kc + k][64 + r0];
      *(float4*)&bv[0] = *(const float4*)&w2s[k][c0];
      *(float4*)&bv[4] = *(const float4*)&w2s[k][32 + c0];
#pragma unroll
      for (int i = 0; i < 8; i++)
#pragma unroll
        for (int j = 0; j < 8; j++) acc[i][j] += a[i] * bv[j];
    }
  }
  __syncthreads();               // all w2s reads done -> reuse as red
  float* red = &w2s[0][0];       // red[q][c] at red[q*68 + c], q 0..31

  // half0 rows r0..r0+3 -> point rb>>2 (slot rb&3); half1 -> point 4+(rb>>2)
#pragma unroll
  for (int j = 0; j < 8; j++) {
    int c = (j < 4) ? (c0 + j) : (32 + c0 + j - 4);
    float m0 = acc[0][j], m1 = acc[4][j];
#pragma unroll
    for (int i = 1; i < 4; i++) { m0 = fmaxf(m0, acc[i][j]); m1 = fmaxf(m1, acc[4 + i][j]); }
    red[rb * 68 + c] = m0;
    red[(16 + rb) * 68 + c] = m1;
  }
  __syncthreads();

  // combine: point p partials live at red[4p + q], q=0..3
  {
    int p = tid >> 4;
    int c = (tid & 15) << 2;
    int base = 4 * p;
    float4 m = *(const float4*)&red[base * 68 + c];
#pragma unroll
    for (int q = 1; q < 4; q++) {
      float4 r4 = *(const float4*)&red[(base + q) * 68 + c];
      m.x = fmaxf(m.x, r4.x); m.y = fmaxf(m.y, r4.y);
      m.z = fmaxf(m.z, r4.z); m.w = fmaxf(m.w, r4.w);
    }
    float4 bb4 = *(const float4*)&b2[c];
    m.x += bb4.x; m.y += bb4.y; m.z += bb4.z; m.w += bb4.w;
    *(float4*)&g_feat[(size_t)(p0 + p) * 192 + outOff + c] = m;
  }
}

// ---------------- MLP1: 192 -> 128, 128x128 tiles, 8x8 split micro ----------------
__global__ __launch_bounds__(256, 2) void mlp1_kernel(const float* __restrict__ W,
                                                      const float* __restrict__ bias) {
  __shared__ float xT[32][132];
  __shared__ float ws[32][132];
  int tid = threadIdx.x;
  int row0 = blockIdx.x << 7;
  int rb = tid & 15, cb = tid >> 4;
  int r0 = rb << 2, c0 = cb << 2;
  float acc[8][8];
#pragma unroll
  for (int i = 0; i < 8; i++)
#pragma unroll
    for (int j = 0; j < 8; j++) acc[i][j] = 0.f;

  for (int kc = 0; kc < 192; kc += 32) {
    __syncthreads();
#pragma unroll
    for (int t = tid; t < 1024; t += 256) {
      int r = t >> 3, dg = (t & 7) << 2;
      float4 v = *(const float4*)&g_feat[(size_t)(row0 + r) * 192 + kc + dg];
      xT[dg + 0][r] = v.x; xT[dg + 1][r] = v.y;
      xT[dg + 2][r] = v.z; xT[dg + 3][r] = v.w;
    }
#pragma unroll
    for (int t = tid; t < 1024; t += 256) {
      int k = t >> 5, cg = (t & 31) << 2;
      *(float4*)&ws[k][cg] = *(const float4*)&W[(size_t)(kc + k) * 128 + cg];
    }
    __syncthreads();
#pragma unroll
    for (int k = 0; k < 32; k++) {
      float a[8], bv[8];
      *(float4*)&a[0]  = *(const float4*)&xT[k][r0];
      *(float4*)&a[4]  = *(const float4*)&xT[k][64 + r0];
      *(float4*)&bv[0] = *(const float4*)&ws[k][c0];
      *(float4*)&bv[4] = *(const float4*)&ws[k][64 + c0];
#pragma unroll
      for (int i = 0; i < 8; i++)
#pragma unroll
        for (int j = 0; j < 8; j++) acc[i][j] += a[i] * bv[j];
    }
  }
#pragma unroll
  for (int i = 0; i < 8; i++) {
    int r = row0 + ((i < 4) ? (r0 + i) : (64 + r0 + i - 4));
    float4 o0, o1;
    o0.x = fmaxf(acc[i][0] + bias[c0 + 0], 0.f);
    o0.y = fmaxf(acc[i][1] + bias[c0 + 1], 0.f);
    o0.z = fmaxf(acc[i][2] + bias[c0 + 2], 0.f);
    o0.w = fmaxf(acc[i][3] + bias[c0 + 3], 0.f);
    o1.x = fmaxf(acc[i][4] + bias[64 + c0 + 0], 0.f);
    o1.y = fmaxf(acc[i][5] + bias[64 + c0 + 1], 0.f);
    o1.z = fmaxf(acc[i][6] + bias[64 + c0 + 2], 0.f);
    o1.w = fmaxf(acc[i][7] + bias[64 + c0 + 3], 0.f);
    *(float4*)&g_h1[((size_t)r << 7) + c0]      = o0;
    *(float4*)&g_h1[((size_t)r << 7) + 64 + c0] = o1;
  }
}

// ---------------- small MLP GEMMs ----------------
template <int K, int N, bool RELU>
__global__ __launch_bounds__(256) void gemm_kernel(int xsel, int sx,
                                                   const float* __restrict__ W,
                                                   const float* __restrict__ bias,
                                                   int osel, int so) {
  constexpr int CT = N / 16;
  __shared__ float xs[64][36];
  __shared__ float ws[32][N];
  const float* X = buf_sel(xsel);
  float* out = buf_sel(osel);
  int tid = threadIdx.x;
  int row0 = blockIdx.x * 64;
  int rb = tid & 15, cb = tid >> 4;
  int r0 = rb * 4, c0 = cb * CT;
  float acc[4][CT];
#pragma unroll
  for (int i = 0; i < 4; i++)
#pragma unroll
    for (int c = 0; c < CT; c++) acc[i][c] = 0.f;

  for (int kc = 0; kc < K; kc += 32) {
    __syncthreads();
    for (int t = tid; t < 2048; t += 256) {
      int rr = t >> 5, dd = t & 31;
      xs[rr][dd] = X[(size_t)(row0 + rr) * sx + kc + dd];
    }
    for (int t = tid; t < 32 * N; t += 256) {
      int kk = t / N, cc = t % N;
      ws[kk][cc] = W[(size_t)(kc + kk) * N + cc];
    }
    __syncthreads();
#pragma unroll
    for (int k = 0; k < 32; k += 4) {
      float a[4][4];
#pragma unroll
      for (int i = 0; i < 4; i++) {
        float4 v = *(const float4*)&xs[r0 + i][k];
        a[i][0] = v.x; a[i][1] = v.y; a[i][2] = v.z; a[i][3] = v.w;
      }
#pragma unroll
      for (int kk = 0; kk < 4; kk++)
#pragma unroll
        for (int cc = 0; cc < CT; cc++) {
          float wv = ws[k + kk][c0 + cc];
#pragma unroll
          for (int i = 0; i < 4; i++) acc[i][cc] += a[i][kk] * wv;
        }
    }
  }
#pragma unroll
  for (int i = 0; i < 4; i++)
#pragma unroll
    for (int cc = 0; cc < CT; cc++) {
      float v = acc[i][cc] + bias[c0 + cc];
      if (RELU) v = fmaxf(v, 0.f);
      out[(size_t)(row0 + r0 + i) * so + c0 + cc] = v;
    }
}

// ---------------- final layer (32 -> 2) + log_softmax ----------------
__global__ __launch_bounds__(256) void final_kernel(const float* __restrict__ w4,
                                                    const float* __restrict__ b4,
                                                    float* __restrict__ out) {
  int i = blockIdx.x * 256 + threadIdx.x;
  const float* h = g_h3 + (size_t)i * 32;
  float z0 = b4[0], z1 = b4[1];
#pragma unroll
  for (int k = 0; k < 32; k += 4) {
    float4 v = *(const float4*)&h[k];
    z0 += v.x * w4[(k + 0) * 2 + 0];  z1 += v.x * w4[(k + 0) * 2 + 1];
    z0 += v.y * w4[(k + 1) * 2 + 0];  z1 += v.y * w4[(k + 1) * 2 + 1];
    z0 += v.z * w4[(k + 2) * 2 + 0];  z1 += v.z * w4[(k + 2) * 2 + 1];
    z0 += v.w * w4[(k + 3) * 2 + 0];  z1 += v.w * w4[(k + 3) * 2 + 1];
  }
  float m = fmaxf(z0, z1);
  float l = m + logf(expf(z0 - m) + expf(z1 - m));
  out[2 * i + 0] = z0 - l;
  out[2 * i + 1] = z1 - l;
}

// ---------------- launch ----------------
extern "C" void kernel_launch(void* const* d_in, const int* in_sizes, int n_in,
                              void* d_out, int out_size) {
  const float* x    = (const float*)d_in[0];
  const float* c1w1 = (const float*)d_in[1];
  const float* c1b1 = (const float*)d_in[2];
  const float* c1w2 = (const float*)d_in[3];
  const float* c1b2 = (const float*)d_in[4];
  const float* c2w1 = (const float*)d_in[5];
  const float* c2b1 = (const float*)d_in[6];
  const float* c2w2 = (const float*)d_in[7];
  const float* c2b2 = (const float*)d_in[8];
  const float* c3w1 = (const float*)d_in[9];
  const float* c3b1 = (const float*)d_in[10];
  const float* c3w2 = (const float*)d_in[11];
  const float* c3b2 = (const float*)d_in[12];
  const float* mw1  = (const float*)d_in[13];
  const float* mb1  = (const float*)d_in[14];
  const float* mw2  = (const float*)d_in[15];
  const float* mb2  = (const float*)d_in[16];
  const float* mw3  = (const float*)d_in[17];
  const float* mb3  = (const float*)d_in[18];
  const float* mw4  = (const float*)d_in[19];
  const float* mb4  = (const float*)d_in[20];
  float* out = (float*)d_out;

  const int KNN64_SMEM = (64 * 68 + 64 * 132 + 128 * 68 + 128) * 4;  // 86.5 KB
  cudaFuncSetAttribute(knn64_kernel, cudaFuncAttributeMaxDynamicSharedMemorySize,
                       KNN64_SMEM);

  // ---- EdgeConv 1 (d_in = 1) ----
  knn1_kernel<<<8192, 256>>>(x);
  prec1_kernel<<<4096, 256>>>(x, c1w1, c1b1);
  edge_kernel<<<8192, 128>>>(c1w2, c1b2, 0);

  // ---- EdgeConv 2 (on x1, d_in = 64) ----
  knn64_kernel<<<1024, 256, KNN64_SMEM>>>(0);
  prec64_kernel<<<1024, 256>>>(0, c2w1, c2b1);
  edge_kernel<<<8192, 128>>>(c2w2, c2b2, 64);

  // ---- EdgeConv 3 (on x2, d_in = 64) ----
  knn64_kernel<<<1024, 256, KNN64_SMEM>>>(64);
  prec64_kernel<<<1024, 256>>>(64, c3w1, c3b1);
  edge_kernel<<<8192, 128>>>(c3w2, c3b2, 128);

  // ---- MLP head ----
  mlp1_kernel<<<512, 256>>>(mw1, mb1);
  gemm_kernel<128, 64, true><<<1024, 256>>>(1, 128, mw2, mb2, 2, 64);
  gemm_kernel<64, 32, true><<<1024, 256>>>(2, 64, mw3, mb3, 3, 32);
  final_kernel<<<256, 256>>>(mw4, mb4, out);
}

// round 8
// speedup vs baseline: 1.8224x; 1.8224x over previous
#include <cuda_runtime.h>
#include <math.h>

#define NBATCH 64
#define NPTSB  1024
#define NP     65536
#define KNN    16
#define FINF   3.402823466e38f

// ---------------- scratch (static __device__, no allocs) ----------------
__device__ float g_dist[(size_t)NP * NPTSB];   // 256 MB distance scores
__device__ int   g_idx[NP * KNN];              // knn indices (within batch)
__device__ float g_feat[NP * 192];             // [x1 | x2 | x3] concat, stride 192
__device__ float g_A[NP * 64];                 // point-level A = X@(W1a-W1b)+b1
__device__ float g_P[NP * 64];                 // point-level P = X@W1b
__device__ float g_h1[NP * 128];
__device__ float g_h2[NP * 64];
__device__ float g_h3[NP * 32];

__device__ __forceinline__ float* buf_sel(int s) {
  switch (s) {
    case 0: return g_feat;
    case 1: return g_h1;
    case 2: return g_h2;
    case 3: return g_h3;
  }
  return 0;
}

// ---------------- fused KNN, d_in = 1 (compute scores in-register + top-k) ----------------
__global__ __launch_bounds__(256) void knn1_kernel(const float* __restrict__ x) {
  int gw = (blockIdx.x << 3) + (threadIdx.x >> 5);   // row 0..65535
  int lane = threadIdx.x & 31;
  int b = gw >> 10;
  float xi = x[gw];
  const float* xb = x + (b << 10);
  float v[32];
#pragma unroll
  for (int q = 0; q < 32; q++) {
    float xj = xb[(q << 5) + lane];
    v[q] = xj * (xj - 2.0f * xi);
  }
  float bv = v[0]; int bq = 0;
#pragma unroll
  for (int q = 1; q < 32; q++) if (v[q] < bv) { bv = v[q]; bq = q; }
  int bidx = (bq << 5) + lane;
#pragma unroll 1
  for (int it = 0; it < 16; it++) {
    float wv = bv; int wi = bidx;
#pragma unroll
    for (int o = 16; o; o >>= 1) {
      float ov = __shfl_down_sync(0xffffffffu, wv, o);
      int   oi = __shfl_down_sync(0xffffffffu, wi, o);
      if (ov < wv || (ov == wv && oi < wi)) { wv = ov; wi = oi; }
    }
    wi = __shfl_sync(0xffffffffu, wi, 0);
    if (lane == 0) g_idx[(gw << 4) + it] = wi;
    if ((wi & 31) == lane) {
      int qr = wi >> 5;
#pragma unroll
      for (int q = 0; q < 32; q++) if (q == qr) v[q] = FINF;
      bv = v[0]; bq = 0;
#pragma unroll
      for (int q = 1; q < 32; q++) if (v[q] < bv) { bv = v[q]; bq = q; }
      bidx = (bq << 5) + lane;
    }
  }
}

// ---------------- KNN distance GEMM, d_in = 64 ----------------
// 128x128 tile, 8x8 SPLIT micro-tile (conflict-free), writes g_dist.
__global__ __launch_bounds__(256, 2) void dist64_kernel(int featOff) {
  __shared__ float xiT[32][132];
  __shared__ float xjT[32][132];
  __shared__ float sqj[128];
  int tid = threadIdx.x;
  int b = blockIdx.z;
  int i0 = blockIdx.y << 7;
  int j0 = blockIdx.x << 7;
  const float* Xb = g_feat + ((size_t)b << 10) * 192 + featOff;

  int rb = tid & 15, cb = tid >> 4;
  int r0 = rb << 2, c0 = cb << 2;
  float acc[8][8];
#pragma unroll
  for (int i = 0; i < 8; i++)
#pragma unroll
    for (int j = 0; j < 8; j++) acc[i][j] = 0.f;
  float sq = 0.f;

  for (int kc = 0; kc < 64; kc += 32) {
    __syncthreads();
#pragma unroll
    for (int t = tid; t < 1024; t += 256) {
      int r = t >> 3, dg = (t & 7) << 2;
      float4 vi = *(const float4*)&Xb[(size_t)(i0 + r) * 192 + kc + dg];
      xiT[dg + 0][r] = vi.x; xiT[dg + 1][r] = vi.y;
      xiT[dg + 2][r] = vi.z; xiT[dg + 3][r] = vi.w;
      float4 vj = *(const float4*)&Xb[(size_t)(j0 + r) * 192 + kc + dg];
      xjT[dg + 0][r] = vj.x; xjT[dg + 1][r] = vj.y;
      xjT[dg + 2][r] = vj.z; xjT[dg + 3][r] = vj.w;
    }
    __syncthreads();
    if (tid < 128) {
#pragma unroll
      for (int d = 0; d < 32; d++) { float u = xjT[d][tid]; sq += u * u; }
    }
#pragma unroll
    for (int k = 0; k < 32; k++) {
      float a[8], bv[8];
      *(float4*)&a[0]  = *(const float4*)&xiT[k][r0];
      *(float4*)&a[4]  = *(const float4*)&xiT[k][64 + r0];
      *(float4*)&bv[0] = *(const float4*)&xjT[k][c0];
      *(float4*)&bv[4] = *(const float4*)&xjT[k][64 + c0];
#pragma unroll
      for (int i = 0; i < 8; i++)
#pragma unroll
        for (int j = 0; j < 8; j++) acc[i][j] += a[i] * bv[j];
    }
  }
  if (tid < 128) sqj[tid] = sq;
  __syncthreads();
#pragma unroll
  for (int i = 0; i < 8; i++) {
    int r = (i < 4) ? (r0 + i) : (64 + r0 + i - 4);
    float4 o0, o1;
    o0.x = sqj[c0 + 0] - 2.f * acc[i][0];
    o0.y = sqj[c0 + 1] - 2.f * acc[i][1];
    o0.z = sqj[c0 + 2] - 2.f * acc[i][2];
    o0.w = sqj[c0 + 3] - 2.f * acc[i][3];
    o1.x = sqj[64 + c0 + 0] - 2.f * acc[i][4];
    o1.y = sqj[64 + c0 + 1] - 2.f * acc[i][5];
    o1.z = sqj[64 + c0 + 2] - 2.f * acc[i][6];
    o1.w = sqj[64 + c0 + 3] - 2.f * acc[i][7];
    size_t base = (((size_t)(b << 10) + i0 + r) << 10) + j0;
    *(float4*)&g_dist[base + c0]      = o0;
    *(float4*)&g_dist[base + 64 + c0] = o1;
  }
}

// ---------------- top-16: warp per row, register-resident ----------------
__global__ __launch_bounds__(256) void topk_kernel() {
  int gw = (blockIdx.x << 3) + (threadIdx.x >> 5);   // row 0..65535
  int lane = threadIdx.x & 31;
  const float* src = g_dist + ((size_t)gw << 10);
  float v[32];
#pragma unroll
  for (int q = 0; q < 32; q++) v[q] = src[(q << 5) + lane];
  float bv = v[0]; int bq = 0;
#pragma unroll
  for (int q = 1; q < 32; q++) if (v[q] < bv) { bv = v[q]; bq = q; }
  int bidx = (bq << 5) + lane;
#pragma unroll 1
  for (int it = 0; it < 16; it++) {
    float wv = bv; int wi = bidx;
#pragma unroll
    for (int o = 16; o; o >>= 1) {
      float ov = __shfl_down_sync(0xffffffffu, wv, o);
      int   oi = __shfl_down_sync(0xffffffffu, wi, o);
      if (ov < wv || (ov == wv && oi < wi)) { wv = ov; wi = oi; }
    }
    wi = __shfl_sync(0xffffffffu, wi, 0);
    if (lane == 0) g_idx[(gw << 4) + it] = wi;
    if ((wi & 31) == lane) {
      int qr = wi >> 5;
#pragma unroll
      for (int q = 0; q < 32; q++) if (q == qr) v[q] = FINF;
      bv = v[0]; bq = 0;
#pragma unroll
      for (int q = 1; q < 32; q++) if (v[q] < bv) { bv = v[q]; bq = q; }
      bidx = (bq << 5) + lane;
    }
  }
}

// ---------------- point-level A/P precompute ----------------
__global__ __launch_bounds__(256) void prec1_kernel(const float* __restrict__ x,
                                                    const float* __restrict__ w1,
                                                    const float* __restrict__ b1) {
  int t = blockIdx.x * 256 + threadIdx.x;
  int i = t >> 4;
  int c = (t & 15) << 2;
  float xi = x[i];
  float4 wa = *(const float4*)&w1[c];
  float4 wb = *(const float4*)&w1[64 + c];
  float4 bb = *(const float4*)&b1[c];
  float4 A, P;
  A.x = xi * (wa.x - wb.x) + bb.x;  P.x = xi * wb.x;
  A.y = xi * (wa.y - wb.y) + bb.y;  P.y = xi * wb.y;
  A.z = xi * (wa.z - wb.z) + bb.z;  P.z = xi * wb.z;
  A.w = xi * (wa.w - wb.w) + bb.w;  P.w = xi * wb.w;
  *(float4*)&g_A[(size_t)i * 64 + c] = A;
  *(float4*)&g_P[(size_t)i * 64 + c] = P;
}

__global__ __launch_bounds__(256) void prec64_kernel(int featOff,
                                                     const float* __restrict__ w1,
                                                     const float* __restrict__ b1) {
  __shared__ float xs[64][36];
  __shared__ float wd[32][64];
  __shared__ float wb[32][64];
  int tid = threadIdx.x;
  int row0 = blockIdx.x * 64;
  int rb = tid & 15, cb = tid >> 4;
  int r0 = rb * 4, c0 = cb * 4;
  float accA[4][4] = {}, accP[4][4] = {};

  for (int kc = 0; kc < 64; kc += 32) {
    __syncthreads();
    for (int t = tid; t < 2048; t += 256) {
      int rr = t >> 5, dd = t & 31;
      xs[rr][dd] = g_feat[(size_t)(row0 + rr) * 192 + featOff + kc + dd];
    }
    for (int t = tid; t < 2048; t += 256) {
      int kk = t >> 6, cc = t & 63;
      float bw = w1[(size_t)(64 + kc + kk) * 64 + cc];
      wb[kk][cc] = bw;
      wd[kk][cc] = w1[(size_t)(kc + kk) * 64 + cc] - bw;
    }
    __syncthreads();
#pragma unroll
    for (int k = 0; k < 32; k += 4) {
      float a[4][4];
#pragma unroll
      for (int i = 0; i < 4; i++) {
        float4 v = *(const float4*)&xs[r0 + i][k];
        a[i][0] = v.x; a[i][1] = v.y; a[i][2] = v.z; a[i][3] = v.w;
      }
#pragma unroll
      for (int kk = 0; kk < 4; kk++)
#pragma unroll
        for (int cc = 0; cc < 4; cc++) {
          float wdv = wd[k + kk][c0 + cc];
          float wbv = wb[k + kk][c0 + cc];
#pragma unroll
          for (int i = 0; i < 4; i++) {
            accA[i][cc] += a[i][kk] * wdv;
            accP[i][cc] += a[i][kk] * wbv;
          }
        }
    }
  }
#pragma unroll
  for (int i = 0; i < 4; i++)
#pragma unroll
    for (int cc = 0; cc < 4; cc++) {
      int r = row0 + r0 + i, c = c0 + cc;
      g_A[(size_t)r * 64 + c] = accA[i][cc] + b1[c];
      g_P[(size_t)r * 64 + c] = accP[i][cc];
    }
}

// ---------------- fused edge kernel ----------------
// 8 points x 16 edges = 128 h1 rows, 128x64 GEMM, 8x8 split micro, seg-max.
__global__ __launch_bounds__(128, 4) void edge_kernel(const float* __restrict__ w2,
                                                      const float* __restrict__ b2,
                                                      int outOff) {
  __shared__ float h1T[64][132];
  __shared__ float w2s[32][68];   // reused as red[32][68] after GEMM
  int tid = threadIdx.x;
  int p0 = blockIdx.x << 3;

  // build h1 rows transposed: h1T[d][r] = relu(A[i(r)][d] + P[j(r)][d])
  {
    int r = tid;
    int p = r >> 4, e = r & 15;
    int gi = p0 + p;
    int bb = gi >> 10;
    int j = g_idx[(gi << 4) + e];
    const float* Ar = g_A + ((size_t)gi << 6);
    const float* Pr = g_P + ((size_t)((bb << 10) + j) << 6);
#pragma unroll
    for (int d = 0; d < 64; d += 4) {
      float4 av = *(const float4*)(Ar + d);
      float4 pv = *(const float4*)(Pr + d);
      h1T[d + 0][r] = fmaxf(av.x + pv.x, 0.f);
      h1T[d + 1][r] = fmaxf(av.y + pv.y, 0.f);
      h1T[d + 2][r] = fmaxf(av.z + pv.z, 0.f);
      h1T[d + 3][r] = fmaxf(av.w + pv.w, 0.f);
    }
  }

  int rb = tid & 15, cb = tid >> 4;   // cb 0..7
  int r0 = rb << 2, c0 = cb << 2;
  float acc[8][8];
#pragma unroll
  for (int i = 0; i < 8; i++)
#pragma unroll
    for (int j = 0; j < 8; j++) acc[i][j] = 0.f;

  for (int kc = 0; kc < 64; kc += 32) {
    __syncthreads();
    for (int t = tid; t < 512; t += 128) {
      int k = t >> 4, cg = (t & 15) << 2;
      *(float4*)&w2s[k][cg] = *(const float4*)&w2[((size_t)(kc + k) << 6) + cg];
    }
    __syncthreads();
#pragma unroll
    for (int k = 0; k < 32; k++) {
      float a[8], bv[8];
      *(float4*)&a[0]  = *(const float4*)&h1T[kc + k][r0];
      *(float4*)&a[4]  = *(const float4*)&h1T[kc + k][64 + r0];
      *(float4*)&bv[0] = *(const float4*)&w2s[k][c0];
      *(float4*)&bv[4] = *(const float4*)&w2s[k][32 + c0];
#pragma unroll
      for (int i = 0; i < 8; i++)
#pragma unroll
        for (int j = 0; j < 8; j++) acc[i][j] += a[i] * bv[j];
    }
  }
  __syncthreads();               // all w2s reads done -> reuse as red
  float* red = &w2s[0][0];       // red[q][c] at red[q*68 + c], q 0..31

  // half0 rows r0..r0+3 -> point rb>>2 (slot rb&3); half1 -> point 4+(rb>>2)
#pragma unroll
  for (int j = 0; j < 8; j++) {
    int c = (j < 4) ? (c0 + j) : (32 + c0 + j - 4);
    float m0 = acc[0][j], m1 = acc[4][j];
#pragma unroll
    for (int i = 1; i < 4; i++) { m0 = fmaxf(m0, acc[i][j]); m1 = fmaxf(m1, acc[4 + i][j]); }
    red[rb * 68 + c] = m0;
    red[(16 + rb) * 68 + c] = m1;
  }
  __syncthreads();

  // combine: point p partials live at red[4p + q], q=0..3
  {
    int p = tid >> 4;
    int c = (tid & 15) << 2;
    int base = 4 * p;
    float4 m = *(const float4*)&red[base * 68 + c];
#pragma unroll
    for (int q = 1; q < 4; q++) {
      float4 r4 = *(const float4*)&red[(base + q) * 68 + c];
      m.x = fmaxf(m.x, r4.x); m.y = fmaxf(m.y, r4.y);
      m.z = fmaxf(m.z, r4.z); m.w = fmaxf(m.w, r4.w);
    }
    float4 bb4 = *(const float4*)&b2[c];
    m.x += bb4.x; m.y += bb4.y; m.z += bb4.z; m.w += bb4.w;
    *(float4*)&g_feat[(size_t)(p0 + p) * 192 + outOff + c] = m;
  }
}

// ---------------- MLP1: 192 -> 128, 128x128 tiles, 8x8 split micro ----------------
__global__ __launch_bounds__(256, 2) void mlp1_kernel(const float* __restrict__ W,
                                                      const float* __restrict__ bias) {
  __shared__ float xT[32][132];
  __shared__ float ws[32][132];
  int tid = threadIdx.x;
  int row0 = blockIdx.x << 7;
  int rb = tid & 15, cb = tid >> 4;
  int r0 = rb << 2, c0 = cb << 2;
  float acc[8][8];
#pragma unroll
  for (int i = 0; i < 8; i++)
#pragma unroll
    for (int j = 0; j < 8; j++) acc[i][j] = 0.f;

  for (int kc = 0; kc < 192; kc += 32) {
    __syncthreads();
#pragma unroll
    for (int t = tid; t < 1024; t += 256) {
      int r = t >> 3, dg = (t & 7) << 2;
      float4 v = *(const float4*)&g_feat[(size_t)(row0 + r) * 192 + kc + dg];
      xT[dg + 0][r] = v.x; xT[dg + 1][r] = v.y;
      xT[dg + 2][r] = v.z; xT[dg + 3][r] = v.w;
    }
#pragma unroll
    for (int t = tid; t < 1024; t += 256) {
      int k = t >> 5, cg = (t & 31) << 2;
      *(float4*)&ws[k][cg] = *(const float4*)&W[(size_t)(kc + k) * 128 + cg];
    }
    __syncthreads();
#pragma unroll
    for (int k = 0; k < 32; k++) {
      float a[8], bv[8];
      *(float4*)&a[0]  = *(const float4*)&xT[k][r0];
      *(float4*)&a[4]  = *(const float4*)&xT[k][64 + r0];
      *(float4*)&bv[0] = *(const float4*)&ws[k][c0];
      *(float4*)&bv[4] = *(const float4*)&ws[k][64 + c0];
#pragma unroll
      for (int i = 0; i < 8; i++)
#pragma unroll
        for (int j = 0; j < 8; j++) acc[i][j] += a[i] * bv[j];
    }
  }
#pragma unroll
  for (int i = 0; i < 8; i++) {
    int r = row0 + ((i < 4) ? (r0 + i) : (64 + r0 + i - 4));
    float4 o0, o1;
    o0.x = fmaxf(acc[i][0] + bias[c0 + 0], 0.f);
    o0.y = fmaxf(acc[i][1] + bias[c0 + 1], 0.f);
    o0.z = fmaxf(acc[i][2] + bias[c0 + 2], 0.f);
    o0.w = fmaxf(acc[i][3] + bias[c0 + 3], 0.f);
    o1.x = fmaxf(acc[i][4] + bias[64 + c0 + 0], 0.f);
    o1.y = fmaxf(acc[i][5] + bias[64 + c0 + 1], 0.f);
    o1.z = fmaxf(acc[i][6] + bias[64 + c0 + 2], 0.f);
    o1.w = fmaxf(acc[i][7] + bias[64 + c0 + 3], 0.f);
    *(float4*)&g_h1[((size_t)r << 7) + c0]      = o0;
    *(float4*)&g_h1[((size_t)r << 7) + 64 + c0] = o1;
  }
}

// ---------------- small MLP GEMMs ----------------
template <int K, int N, bool RELU>
__global__ __launch_bounds__(256) void gemm_kernel(int xsel, int sx,
                                                   const float* __restrict__ W,
                                                   const float* __restrict__ bias,
                                                   int osel, int so) {
  constexpr int CT = N / 16;
  __shared__ float xs[64][36];
  __shared__ float ws[32][N];
  const float* X = buf_sel(xsel);
  float* out = buf_sel(osel);
  int tid = threadIdx.x;
  int row0 = blockIdx.x * 64;
  int rb = tid & 15, cb = tid >> 4;
  int r0 = rb * 4, c0 = cb * CT;
  float acc[4][CT];
#pragma unroll
  for (int i = 0; i < 4; i++)
#pragma unroll
    for (int c = 0; c < CT; c++) acc[i][c] = 0.f;

  for (int kc = 0; kc < K; kc += 32) {
    __syncthreads();
    for (int t = tid; t < 2048; t += 256) {
      int rr = t >> 5, dd = t & 31;
      xs[rr][dd] = X[(size_t)(row0 + rr) * sx + kc + dd];
    }
    for (int t = tid; t < 32 * N; t += 256) {
      int kk = t / N, cc = t % N;
      ws[kk][cc] = W[(size_t)(kc + kk) * N + cc];
    }
    __syncthreads();
#pragma unroll
    for (int k = 0; k < 32; k += 4) {
      float a[4][4];
#pragma unroll
      for (int i = 0; i < 4; i++) {
        float4 v = *(const float4*)&xs[r0 + i][k];
        a[i][0] = v.x; a[i][1] = v.y; a[i][2] = v.z; a[i][3] = v.w;
      }
#pragma unroll
      for (int kk = 0; kk < 4; kk++)
#pragma unroll
        for (int cc = 0; cc < CT; cc++) {
          float wv = ws[k + kk][c0 + cc];
#pragma unroll
          for (int i = 0; i < 4; i++) acc[i][cc] += a[i][kk] * wv;
        }
    }
  }
#pragma unroll
  for (int i = 0; i < 4; i++)
#pragma unroll
    for (int cc = 0; cc < CT; cc++) {
      float v = acc[i][cc] + bias[c0 + cc];
      if (RELU) v = fmaxf(v, 0.f);
      out[(size_t)(row0 + r0 + i) * so + c0 + cc] = v;
    }
}

// ---------------- final layer (32 -> 2) + log_softmax ----------------
__global__ __launch_bounds__(256) void final_kernel(const float* __restrict__ w4,
                                                    const float* __restrict__ b4,
                                                    float* __restrict__ out) {
  int i = blockIdx.x * 256 + threadIdx.x;
  const float* h = g_h3 + (size_t)i * 32;
  float z0 = b4[0], z1 = b4[1];
#pragma unroll
  for (int k = 0; k < 32; k += 4) {
    float4 v = *(const float4*)&h[k];
    z0 += v.x * w4[(k + 0) * 2 + 0];  z1 += v.x * w4[(k + 0) * 2 + 1];
    z0 += v.y * w4[(k + 1) * 2 + 0];  z1 += v.y * w4[(k + 1) * 2 + 1];
    z0 += v.z * w4[(k + 2) * 2 + 0];  z1 += v.z * w4[(k + 2) * 2 + 1];
    z0 += v.w * w4[(k + 3) * 2 + 0];  z1 += v.w * w4[(k + 3) * 2 + 1];
  }
  float m = fmaxf(z0, z1);
  float l = m + logf(expf(z0 - m) + expf(z1 - m));
  out[2 * i + 0] = z0 - l;
  out[2 * i + 1] = z1 - l;
}

// ---------------- launch ----------------
extern "C" void kernel_launch(void* const* d_in, const int* in_sizes, int n_in,
                              void* d_out, int out_size) {
  const float* x    = (const float*)d_in[0];
  const float* c1w1 = (const float*)d_in[1];
  const float* c1b1 = (const float*)d_in[2];
  const float* c1w2 = (const float*)d_in[3];
  const float* c1b2 = (const float*)d_in[4];
  const float* c2w1 = (const float*)d_in[5];
  const float* c2b1 = (const float*)d_in[6];
  const float* c2w2 = (const float*)d_in[7];
  const float* c2b2 = (const float*)d_in[8];
  const float* c3w1 = (const float*)d_in[9];
  const float* c3b1 = (const float*)d_in[10];
  const float* c3w2 = (const float*)d_in[11];
  const float* c3b2 = (const float*)d_in[12];
  const float* mw1  = (const float*)d_in[13];
  const float* mb1  = (const float*)d_in[14];
  const float* mw2  = (const float*)d_in[15];
  const float* mb2  = (const float*)d_in[16];
  const float* mw3  = (const float*)d_in[17];
  const float* mb3  = (const float*)d_in[18];
  const float* mw4  = (const float*)d_in[19];
  const float* mb4  = (const float*)d_in[20];
  float* out = (float*)d_out;

  // ---- EdgeConv 1 (d_in = 1) ----
  knn1_kernel<<<8192, 256>>>(x);
  prec1_kernel<<<4096, 256>>>(x, c1w1, c1b1);
  edge_kernel<<<8192, 128>>>(c1w2, c1b2, 0);

  // ---- EdgeConv 2 (on x1, d_in = 64) ----
  dist64_kernel<<<dim3(8, 8, 64), 256>>>(0);
  topk_kernel<<<8192, 256>>>();
  prec64_kernel<<<1024, 256>>>(0, c2w1, c2b1);
  edge_kernel<<<8192, 128>>>(c2w2, c2b2, 64);

  // ---- EdgeConv 3 (on x2, d_in = 64) ----
  dist64_kernel<<<dim3(8, 8, 64), 256>>>(64);
  topk_kernel<<<8192, 256>>>();
  prec64_kernel<<<1024, 256>>>(64, c3w1, c3b1);
  edge_kernel<<<8192, 128>>>(c3w2, c3b2, 128);

  // ---- MLP head ----
  mlp1_kernel<<<512, 256>>>(mw1, mb1);
  gemm_kernel<128, 64, true><<<1024, 256>>>(1, 128, mw2, mb2, 2, 64);
  gemm_kernel<64, 32, true><<<1024, 256>>>(2, 64, mw3, mb3, 3, 32);
  final_kernel<<<256, 256>>>(mw4, mb4, out);
}

// round 9
// speedup vs baseline: 1.8794x; 1.0313x over previous
#include <cuda_runtime.h>
#include <math.h>

#define NBATCH 64
#define NPTSB  1024
#define NP     65536
#define KNN    16
#define FINF   3.402823466e38f

typedef unsigned long long u64;

// packed f32x2 helpers (sm_103a FFMA2 path)
__device__ __forceinline__ u64 pk2(float lo, float hi) {
  u64 r; asm("mov.b64 %0, {%1, %2};" : "=l"(r) : "f"(lo), "f"(hi)); return r;
}
__device__ __forceinline__ void fma2(u64& d, u64 a, u64 b) {
  asm("fma.rn.f32x2 %0, %1, %2, %0;" : "+l"(d) : "l"(a), "l"(b));
}
__device__ __forceinline__ float2 up2(u64 v) {
  float2 f; asm("mov.b64 {%0, %1}, %2;" : "=f"(f.x), "=f"(f.y) : "l"(v)); return f;
}

// ---------------- scratch (static __device__, no allocs) ----------------
__device__ float g_dist[(size_t)NP * NPTSB];   // 256 MB distance scores
__device__ int   g_idx[NP * KNN];              // knn indices (within batch)
__device__ float g_feat[NP * 192];             // [x1 | x2 | x3] concat, stride 192
__device__ float g_A[NP * 64];                 // point-level A = X@(W1a-W1b)+b1
__device__ float g_P[NP * 64];                 // point-level P = X@W1b
__device__ float g_h1[NP * 128];
__device__ float g_h2[NP * 64];
__device__ float g_h3[NP * 32];

__device__ __forceinline__ float* buf_sel(int s) {
  switch (s) {
    case 0: return g_feat;
    case 1: return g_h1;
    case 2: return g_h2;
    case 3: return g_h3;
  }
  return 0;
}

// ---------------- fused KNN, d_in = 1 ----------------
__global__ __launch_bounds__(256) void knn1_kernel(const float* __restrict__ x) {
  int gw = (blockIdx.x << 3) + (threadIdx.x >> 5);
  int lane = threadIdx.x & 31;
  int b = gw >> 10;
  float xi = x[gw];
  const float* xb = x + (b << 10);
  float v[32];
#pragma unroll
  for (int q = 0; q < 32; q++) {
    float xj = xb[(q << 5) + lane];
    v[q] = xj * (xj - 2.0f * xi);
  }
  float bv = v[0]; int bq = 0;
#pragma unroll
  for (int q = 1; q < 32; q++) if (v[q] < bv) { bv = v[q]; bq = q; }
  int bidx = (bq << 5) + lane;
#pragma unroll 1
  for (int it = 0; it < 16; it++) {
    float wv = bv; int wi = bidx;
#pragma unroll
    for (int o = 16; o; o >>= 1) {
      float ov = __shfl_down_sync(0xffffffffu, wv, o);
      int   oi = __shfl_down_sync(0xffffffffu, wi, o);
      if (ov < wv || (ov == wv && oi < wi)) { wv = ov; wi = oi; }
    }
    wi = __shfl_sync(0xffffffffu, wi, 0);
    if (lane == 0) g_idx[(gw << 4) + it] = wi;
    if ((wi & 31) == lane) {
      int qr = wi >> 5;
#pragma unroll
      for (int q = 0; q < 32; q++) if (q == qr) v[q] = FINF;
      bv = v[0]; bq = 0;
#pragma unroll
      for (int q = 1; q < 32; q++) if (v[q] < bv) { bv = v[q]; bq = q; }
      bidx = (bq << 5) + lane;
    }
  }
}

// ---------------- KNN distance GEMM, d_in = 64 (FFMA2) ----------------
__global__ __launch_bounds__(256, 2) void dist64_kernel(int featOff) {
  __shared__ float xiT[32][132];
  __shared__ float xjT[32][132];
  __shared__ float sqj[128];
  int tid = threadIdx.x;
  int b = blockIdx.z;
  int i0 = blockIdx.y << 7;
  int j0 = blockIdx.x << 7;
  const float* Xb = g_feat + ((size_t)b << 10) * 192 + featOff;

  int rb = tid & 15, cb = tid >> 4;
  int r0 = rb << 2, c0 = cb << 2;
  u64 acc2[8][4];
#pragma unroll
  for (int i = 0; i < 8; i++)
#pragma unroll
    for (int j = 0; j < 4; j++) acc2[i][j] = 0ULL;
  float sq = 0.f;

  for (int kc = 0; kc < 64; kc += 32) {
    __syncthreads();
#pragma unroll
    for (int t = tid; t < 1024; t += 256) {
      int r = t >> 3, dg = (t & 7) << 2;
      float4 vi = *(const float4*)&Xb[(size_t)(i0 + r) * 192 + kc + dg];
      xiT[dg + 0][r] = vi.x; xiT[dg + 1][r] = vi.y;
      xiT[dg + 2][r] = vi.z; xiT[dg + 3][r] = vi.w;
      float4 vj = *(const float4*)&Xb[(size_t)(j0 + r) * 192 + kc + dg];
      xjT[dg + 0][r] = vj.x; xjT[dg + 1][r] = vj.y;
      xjT[dg + 2][r] = vj.z; xjT[dg + 3][r] = vj.w;
    }
    __syncthreads();
    if (tid < 128) {
#pragma unroll
      for (int d = 0; d < 32; d++) { float u = xjT[d][tid]; sq += u * u; }
    }
#pragma unroll
    for (int k = 0; k < 32; k++) {
      float a[8];
      *(float4*)&a[0] = *(const float4*)&xiT[k][r0];
      *(float4*)&a[4] = *(const float4*)&xiT[k][64 + r0];
      u64 bp[4];
      bp[0] = *(const u64*)&xjT[k][c0];
      bp[1] = *(const u64*)&xjT[k][c0 + 2];
      bp[2] = *(const u64*)&xjT[k][64 + c0];
      bp[3] = *(const u64*)&xjT[k][64 + c0 + 2];
#pragma unroll
      for (int i = 0; i < 8; i++) {
        u64 ad = pk2(a[i], a[i]);
#pragma unroll
        for (int jp = 0; jp < 4; jp++) fma2(acc2[i][jp], ad, bp[jp]);
      }
    }
  }
  if (tid < 128) sqj[tid] = sq;
  __syncthreads();
#pragma unroll
  for (int i = 0; i < 8; i++) {
    int r = (i < 4) ? (r0 + i) : (64 + r0 + i - 4);
    float2 p0 = up2(acc2[i][0]), p1 = up2(acc2[i][1]);
    float2 p2 = up2(acc2[i][2]), p3 = up2(acc2[i][3]);
    float4 o0, o1;
    o0.x = sqj[c0 + 0] - 2.f * p0.x;
    o0.y = sqj[c0 + 1] - 2.f * p0.y;
    o0.z = sqj[c0 + 2] - 2.f * p1.x;
    o0.w = sqj[c0 + 3] - 2.f * p1.y;
    o1.x = sqj[64 + c0 + 0] - 2.f * p2.x;
    o1.y = sqj[64 + c0 + 1] - 2.f * p2.y;
    o1.z = sqj[64 + c0 + 2] - 2.f * p3.x;
    o1.w = sqj[64 + c0 + 3] - 2.f * p3.y;
    size_t base = (((size_t)(b << 10) + i0 + r) << 10) + j0;
    *(float4*)&g_dist[base + c0]      = o0;
    *(float4*)&g_dist[base + 64 + c0] = o1;
  }
}

// ---------------- top-16: warp per row, register-resident ----------------
__global__ __launch_bounds__(256) void topk_kernel() {
  int gw = (blockIdx.x << 3) + (threadIdx.x >> 5);
  int lane = threadIdx.x & 31;
  const float* src = g_dist + ((size_t)gw << 10);
  float v[32];
#pragma unroll
  for (int q = 0; q < 32; q++) v[q] = src[(q << 5) + lane];
  float bv = v[0]; int bq = 0;
#pragma unroll
  for (int q = 1; q < 32; q++) if (v[q] < bv) { bv = v[q]; bq = q; }
  int bidx = (bq << 5) + lane;
#pragma unroll 1
  for (int it = 0; it < 16; it++) {
    float wv = bv; int wi = bidx;
#pragma unroll
    for (int o = 16; o; o >>= 1) {
      float ov = __shfl_down_sync(0xffffffffu, wv, o);
      int   oi = __shfl_down_sync(0xffffffffu, wi, o);
      if (ov < wv || (ov == wv && oi < wi)) { wv = ov; wi = oi; }
    }
    wi = __shfl_sync(0xffffffffu, wi, 0);
    if (lane == 0) g_idx[(gw << 4) + it] = wi;
    if ((wi & 31) == lane) {
      int qr = wi >> 5;
#pragma unroll
      for (int q = 0; q < 32; q++) if (q == qr) v[q] = FINF;
      bv = v[0]; bq = 0;
#pragma unroll
      for (int q = 1; q < 32; q++) if (v[q] < bv) { bv = v[q]; bq = q; }
      bidx = (bq << 5) + lane;
    }
  }
}

// ---------------- point-level A/P precompute ----------------
__global__ __launch_bounds__(256) void prec1_kernel(const float* __restrict__ x,
                                                    const float* __restrict__ w1,
                                                    const float* __restrict__ b1) {
  int t = blockIdx.x * 256 + threadIdx.x;
  int i = t >> 4;
  int c = (t & 15) << 2;
  float xi = x[i];
  float4 wa = *(const float4*)&w1[c];
  float4 wb = *(const float4*)&w1[64 + c];
  float4 bb = *(const float4*)&b1[c];
  float4 A, P;
  A.x = xi * (wa.x - wb.x) + bb.x;  P.x = xi * wb.x;
  A.y = xi * (wa.y - wb.y) + bb.y;  P.y = xi * wb.y;
  A.z = xi * (wa.z - wb.z) + bb.z;  P.z = xi * wb.z;
  A.w = xi * (wa.w - wb.w) + bb.w;  P.w = xi * wb.w;
  *(float4*)&g_A[(size_t)i * 64 + c] = A;
  *(float4*)&g_P[(size_t)i * 64 + c] = P;
}

__global__ __launch_bounds__(256) void prec64_kernel(int featOff,
                                                     const float* __restrict__ w1,
                                                     const float* __restrict__ b1) {
  __shared__ float xs[64][36];
  __shared__ float wd[32][64];
  __shared__ float wb[32][64];
  int tid = threadIdx.x;
  int row0 = blockIdx.x * 64;
  int rb = tid & 15, cb = tid >> 4;
  int r0 = rb * 4, c0 = cb * 4;
  float accA[4][4] = {}, accP[4][4] = {};

  for (int kc = 0; kc < 64; kc += 32) {
    __syncthreads();
    for (int t = tid; t < 2048; t += 256) {
      int rr = t >> 5, dd = t & 31;
      xs[rr][dd] = g_feat[(size_t)(row0 + rr) * 192 + featOff + kc + dd];
    }
    for (int t = tid; t < 2048; t += 256) {
      int kk = t >> 6, cc = t & 63;
      float bw = w1[(size_t)(64 + kc + kk) * 64 + cc];
      wb[kk][cc] = bw;
      wd[kk][cc] = w1[(size_t)(kc + kk) * 64 + cc] - bw;
    }
    __syncthreads();
#pragma unroll
    for (int k = 0; k < 32; k += 4) {
      float a[4][4];
#pragma unroll
      for (int i = 0; i < 4; i++) {
        float4 v = *(const float4*)&xs[r0 + i][k];
        a[i][0] = v.x; a[i][1] = v.y; a[i][2] = v.z; a[i][3] = v.w;
      }
#pragma unroll
      for (int kk = 0; kk < 4; kk++)
#pragma unroll
        for (int cc = 0; cc < 4; cc++) {
          float wdv = wd[k + kk][c0 + cc];
          float wbv = wb[k + kk][c0 + cc];
#pragma unroll
          for (int i = 0; i < 4; i++) {
            accA[i][cc] += a[i][kk] * wdv;
            accP[i][cc] += a[i][kk] * wbv;
          }
        }
    }
  }
#pragma unroll
  for (int i = 0; i < 4; i++)
#pragma unroll
    for (int cc = 0; cc < 4; cc++) {
      int r = row0 + r0 + i, c = c0 + cc;
      g_A[(size_t)r * 64 + c] = accA[i][cc] + b1[c];
      g_P[(size_t)r * 64 + c] = accP[i][cc];
    }
}

// ---------------- fused edge kernel (FFMA2 GEMM) ----------------
__global__ __launch_bounds__(128, 4) void edge_kernel(const float* __restrict__ w2,
                                                      const float* __restrict__ b2,
                                                      int outOff) {
  __shared__ float h1T[64][132];
  __shared__ float w2s[32][68];   // reused as red[32][68] after GEMM
  int tid = threadIdx.x;
  int p0 = blockIdx.x << 3;

  // build h1 rows transposed
  {
    int r = tid;
    int p = r >> 4, e = r & 15;
    int gi = p0 + p;
    int bb = gi >> 10;
    int j = g_idx[(gi << 4) + e];
    const float* Ar = g_A + ((size_t)gi << 6);
    const float* Pr = g_P + ((size_t)((bb << 10) + j) << 6);
#pragma unroll
    for (int d = 0; d < 64; d += 4) {
      float4 av = *(const float4*)(Ar + d);
      float4 pv = *(const float4*)(Pr + d);
      h1T[d + 0][r] = fmaxf(av.x + pv.x, 0.f);
      h1T[d + 1][r] = fmaxf(av.y + pv.y, 0.f);
      h1T[d + 2][r] = fmaxf(av.z + pv.z, 0.f);
      h1T[d + 3][r] = fmaxf(av.w + pv.w, 0.f);
    }
  }

  int rb = tid & 15, cb = tid >> 4;   // cb 0..7
  int r0 = rb << 2, c0 = cb << 2;
  u64 acc2[8][4];
#pragma unroll
  for (int i = 0; i < 8; i++)
#pragma unroll
    for (int j = 0; j < 4; j++) acc2[i][j] = 0ULL;

  for (int kc = 0; kc < 64; kc += 32) {
    __syncthreads();
    for (int t = tid; t < 512; t += 128) {
      int k = t >> 4, cg = (t & 15) << 2;
      *(float4*)&w2s[k][cg] = *(const float4*)&w2[((size_t)(kc + k) << 6) + cg];
    }
    __syncthreads();
#pragma unroll
    for (int k = 0; k < 32; k++) {
      float a[8];
      *(float4*)&a[0] = *(const float4*)&h1T[kc + k][r0];
      *(float4*)&a[4] = *(const float4*)&h1T[kc + k][64 + r0];
      u64 bp[4];
      bp[0] = *(const u64*)&w2s[k][c0];
      bp[1] = *(const u64*)&w2s[k][c0 + 2];
      bp[2] = *(const u64*)&w2s[k][32 + c0];
      bp[3] = *(const u64*)&w2s[k][32 + c0 + 2];
#pragma unroll
      for (int i = 0; i < 8; i++) {
        u64 ad = pk2(a[i], a[i]);
#pragma unroll
        for (int jp = 0; jp < 4; jp++) fma2(acc2[i][jp], ad, bp[jp]);
      }
    }
  }
  __syncthreads();               // all w2s reads done -> reuse as red
  float* red = &w2s[0][0];       // red[q][c] at red[q*68 + c], q 0..31

  // segmented max: rows r0..r0+3 -> point (rb>>2, slot rb&3); rows 64+r0.. -> point 4+(rb>>2)
#pragma unroll
  for (int jp = 0; jp < 4; jp++) {
    int c = (jp < 2) ? (c0 + 2 * jp) : (32 + c0 + 2 * (jp - 2));
    float2 v0 = up2(acc2[0][jp]);
    float2 v1 = up2(acc2[4][jp]);
    float m0x = v0.x, m0y = v0.y, m1x = v1.x, m1y = v1.y;
#pragma unroll
    for (int i = 1; i < 4; i++) {
      float2 a0 = up2(acc2[i][jp]);
      float2 a1 = up2(acc2[4 + i][jp]);
      m0x = fmaxf(m0x, a0.x); m0y = fmaxf(m0y, a0.y);
      m1x = fmaxf(m1x, a1.x); m1y = fmaxf(m1y, a1.y);
    }
    red[rb * 68 + c] = m0x;        red[rb * 68 + c + 1] = m0y;
    red[(16 + rb) * 68 + c] = m1x; red[(16 + rb) * 68 + c + 1] = m1y;
  }
  __syncthreads();

  // combine: point p partials live at red[4p + q], q=0..3
  {
    int p = tid >> 4;
    int c = (tid & 15) << 2;
    int base = 4 * p;
    float4 m = *(const float4*)&red[base * 68 + c];
#pragma unroll
    for (int q = 1; q < 4; q++) {
      float4 r4 = *(const float4*)&red[(base + q) * 68 + c];
      m.x = fmaxf(m.x, r4.x); m.y = fmaxf(m.y, r4.y);
      m.z = fmaxf(m.z, r4.z); m.w = fmaxf(m.w, r4.w);
    }
    float4 bb4 = *(const float4*)&b2[c];
    m.x += bb4.x; m.y += bb4.y; m.z += bb4.z; m.w += bb4.w;
    *(float4*)&g_feat[(size_t)(p0 + p) * 192 + outOff + c] = m;
  }
}

// ---------------- MLP1: 192 -> 128 (FFMA2 GEMM) ----------------
__global__ __launch_bounds__(256, 2) void mlp1_kernel(const float* __restrict__ W,
                                                      const float* __restrict__ bias) {
  __shared__ float xT[32][132];
  __shared__ float ws[32][132];
  int tid = threadIdx.x;
  int row0 = blockIdx.x << 7;
  int rb = tid & 15, cb = tid >> 4;
  int r0 = rb << 2, c0 = cb << 2;
  u64 acc2[8][4];
#pragma unroll
  for (int i = 0; i < 8; i++)
#pragma unroll
    for (int j = 0; j < 4; j++) acc2[i][j] = 0ULL;

  for (int kc = 0; kc < 192; kc += 32) {
    __syncthreads();
#pragma unroll
    for (int t = tid; t < 1024; t += 256) {
      int r = t >> 3, dg = (t & 7) << 2;
      float4 v = *(const float4*)&g_feat[(size_t)(row0 + r) * 192 + kc + dg];
      xT[dg + 0][r] = v.x; xT[dg + 1][r] = v.y;
      xT[dg + 2][r] = v.z; xT[dg + 3][r] = v.w;
    }
#pragma unroll
    for (int t = tid; t < 1024; t += 256) {
      int k = t >> 5, cg = (t & 31) << 2;
      *(float4*)&ws[k][cg] = *(const float4*)&W[(size_t)(kc + k) * 128 + cg];
    }
    __syncthreads();
#pragma unroll
    for (int k = 0; k < 32; k++) {
      float a[8];
      *(float4*)&a[0] = *(const float4*)&xT[k][r0];
      *(float4*)&a[4] = *(const float4*)&xT[k][64 + r0];
      u64 bp[4];
      bp[0] = *(const u64*)&ws[k][c0];
      bp[1] = *(const u64*)&ws[k][c0 + 2];
      bp[2] = *(const u64*)&ws[k][64 + c0];
      bp[3] = *(const u64*)&ws[k][64 + c0 + 2];
#pragma unroll
      for (int i = 0; i < 8; i++) {
        u64 ad = pk2(a[i], a[i]);
#pragma unroll
        for (int jp = 0; jp < 4; jp++) fma2(acc2[i][jp], ad, bp[jp]);
      }
    }
  }
#pragma unroll
  for (int i = 0; i < 8; i++) {
    int r = row0 + ((i < 4) ? (r0 + i) : (64 + r0 + i - 4));
    float2 p0 = up2(acc2[i][0]), p1 = up2(acc2[i][1]);
    float2 p2 = up2(acc2[i][2]), p3 = up2(acc2[i][3]);
    float4 o0, o1;
    o0.x = fmaxf(p0.x + bias[c0 + 0], 0.f);
    o0.y = fmaxf(p0.y + bias[c0 + 1], 0.f);
    o0.z = fmaxf(p1.x + bias[c0 + 2], 0.f);
    o0.w = fmaxf(p1.y + bias[c0 + 3], 0.f);
    o1.x = fmaxf(p2.x + bias[64 + c0 + 0], 0.f);
    o1.y = fmaxf(p2.y + bias[64 + c0 + 1], 0.f);
    o1.z = fmaxf(p3.x + bias[64 + c0 + 2], 0.f);
    o1.w = fmaxf(p3.y + bias[64 + c0 + 3], 0.f);
    *(float4*)&g_h1[((size_t)r << 7) + c0]      = o0;
    *(float4*)&g_h1[((size_t)r << 7) + 64 + c0] = o1;
  }
}

// ---------------- small MLP GEMMs ----------------
template <int K, int N, bool RELU>
__global__ __launch_bounds__(256) void gemm_kernel(int xsel, int sx,
                                                   const float* __restrict__ W,
                                                   const float* __restrict__ bias,
                                                   int osel, int so) {
  constexpr int CT = N / 16;
  __shared__ float xs[64][36];
  __shared__ float ws[32][N];
  const float* X = buf_sel(xsel);
  float* out = buf_sel(osel);
  int tid = threadIdx.x;
  int row0 = blockIdx.x * 64;
  int rb = tid & 15, cb = tid >> 4;
  int r0 = rb * 4, c0 = cb * CT;
  float acc[4][CT];
#pragma unroll
  for (int i = 0; i < 4; i++)
#pragma unroll
    for (int c = 0; c < CT; c++) acc[i][c] = 0.f;

  for (int kc = 0; kc < K; kc += 32) {
    __syncthreads();
    for (int t = tid; t < 2048; t += 256) {
      int rr = t >> 5, dd = t & 31;
      xs[rr][dd] = X[(size_t)(row0 + rr) * sx + kc + dd];
    }
    for (int t = tid; t < 32 * N; t += 256) {
      int kk = t / N, cc = t % N;
      ws[kk][cc] = W[(size_t)(kc + kk) * N + cc];
    }
    __syncthreads();
#pragma unroll
    for (int k = 0; k < 32; k += 4) {
      float a[4][4];
#pragma unroll
      for (int i = 0; i < 4; i++) {
        float4 v = *(const float4*)&xs[r0 + i][k];
        a[i][0] = v.x; a[i][1] = v.y; a[i][2] = v.z; a[i][3] = v.w;
      }
#pragma unroll
      for (int kk = 0; kk < 4; kk++)
#pragma unroll
        for (int cc = 0; cc < CT; cc++) {
          float wv = ws[k + kk][c0 + cc];
#pragma unroll
          for (int i = 0; i < 4; i++) acc[i][cc] += a[i][kk] * wv;
        }
    }
  }
#pragma unroll
  for (int i = 0; i < 4; i++)
#pragma unroll
    for (int cc = 0; cc < CT; cc++) {
      float v = acc[i][cc] + bias[c0 + cc];
      if (RELU) v = fmaxf(v, 0.f);
      out[(size_t)(row0 + r0 + i) * so + c0 + cc] = v;
    }
}

// ---------------- final layer (32 -> 2) + log_softmax ----------------
__global__ __launch_bounds__(256) void final_kernel(const float* __restrict__ w4,
                                                    const float* __restrict__ b4,
                                                    float* __restrict__ out) {
  int i = blockIdx.x * 256 + threadIdx.x;
  const float* h = g_h3 + (size_t)i * 32;
  float z0 = b4[0], z1 = b4[1];
#pragma unroll
  for (int k = 0; k < 32; k += 4) {
    float4 v = *(const float4*)&h[k];
    z0 += v.x * w4[(k + 0) * 2 + 0];  z1 += v.x * w4[(k + 0) * 2 + 1];
    z0 += v.y * w4[(k + 1) * 2 + 0];  z1 += v.y * w4[(k + 1) * 2 + 1];
    z0 += v.z * w4[(k + 2) * 2 + 0];  z1 += v.z * w4[(k + 2) * 2 + 1];
    z0 += v.w * w4[(k + 3) * 2 + 0];  z1 += v.w * w4[(k + 3) * 2 + 1];
  }
  float m = fmaxf(z0, z1);
  float l = m + logf(expf(z0 - m) + expf(z1 - m));
  out[2 * i + 0] = z0 - l;
  out[2 * i + 1] = z1 - l;
}

// ---------------- launch ----------------
extern "C" void kernel_launch(void* const* d_in, const int* in_sizes, int n_in,
                              void* d_out, int out_size) {
  const float* x    = (const float*)d_in[0];
  const float* c1w1 = (const float*)d_in[1];
  const float* c1b1 = (const float*)d_in[2];
  const float* c1w2 = (const float*)d_in[3];
  const float* c1b2 = (const float*)d_in[4];
  const float* c2w1 = (const float*)d_in[5];
  const float* c2b1 = (const float*)d_in[6];
  const float* c2w2 = (const float*)d_in[7];
  const float* c2b2 = (const float*)d_in[8];
  const float* c3w1 = (const float*)d_in[9];
  const float* c3b1 = (const float*)d_in[10];
  const float* c3w2 = (const float*)d_in[11];
  const float* c3b2 = (const float*)d_in[12];
  const float* mw1  = (const float*)d_in[13];
  const float* mb1  = (const float*)d_in[14];
  const float* mw2  = (const float*)d_in[15];
  const float* mb2  = (const float*)d_in[16];
  const float* mw3  = (const float*)d_in[17];
  const float* mb3  = (const float*)d_in[18];
  const float* mw4  = (const float*)d_in[19];
  const float* mb4  = (const float*)d_in[20];
  float* out = (float*)d_out;

  // ---- EdgeConv 1 (d_in = 1) ----
  knn1_kernel<<<8192, 256>>>(x);
  prec1_kernel<<<4096, 256>>>(x, c1w1, c1b1);
  edge_kernel<<<8192, 128>>>(c1w2, c1b2, 0);

  // ---- EdgeConv 2 (on x1, d_in = 64) ----
  dist64_kernel<<<dim3(8, 8, 64), 256>>>(0);
  topk_kernel<<<8192, 256>>>();
  prec64_kernel<<<1024, 256>>>(0, c2w1, c2b1);
  edge_kernel<<<8192, 128>>>(c2w2, c2b2, 64);

  // ---- EdgeConv 3 (on x2, d_in = 64) ----
  dist64_kernel<<<dim3(8, 8, 64), 256>>>(64);
  topk_kernel<<<8192, 256>>>();
  prec64_kernel<<<1024, 256>>>(64, c3w1, c3b1);
  edge_kernel<<<8192, 128>>>(c3w2, c3b2, 128);

  // ---- MLP head ----
  mlp1_kernel<<<512, 256>>>(mw1, mb1);
  gemm_kernel<128, 64, true><<<1024, 256>>>(1, 128, mw2, mb2, 2, 64);
  gemm_kernel<64, 32, true><<<1024, 256>>>(2, 64, mw3, mb3, 3, 32);
  final_kernel<<<256, 256>>>(mw4, mb4, out);
}

// round 10
// speedup vs baseline: 2.0273x; 1.0787x over previous
#include <cuda_runtime.h>
#include <math.h>

#define NBATCH 64
#define NPTSB  1024
#define NP     65536
#define KNN    16
#define FINF   3.402823466e38f

typedef unsigned long long u64;

// packed f32x2 helpers (sm_103a FFMA2 path)
__device__ __forceinline__ u64 pk2(float lo, float hi) {
  u64 r; asm("mov.b64 %0, {%1, %2};" : "=l"(r) : "f"(lo), "f"(hi)); return r;
}
__device__ __forceinline__ void fma2(u64& d, u64 a, u64 b) {
  asm("fma.rn.f32x2 %0, %1, %2, %0;" : "+l"(d) : "l"(a), "l"(b));
}
__device__ __forceinline__ float2 up2(u64 v) {
  float2 f; asm("mov.b64 {%0, %1}, %2;" : "=f"(f.x), "=f"(f.y) : "l"(v)); return f;
}

// ---------------- scratch (static __device__, no allocs) ----------------
__device__ float g_dist[(size_t)NP * NPTSB];   // 256 MB distance scores
__device__ int   g_idx[NP * KNN];              // knn indices (within batch)
__device__ float g_feat[NP * 192];             // [x1 | x2 | x3] concat, stride 192
__device__ float g_A[NP * 64];                 // point-level A = X@(W1a-W1b)+b1
__device__ float g_P[NP * 64];                 // point-level P = X@W1b
__device__ float g_h1[NP * 128];
__device__ float g_h2[NP * 64];
__device__ float g_h3[NP * 32];

__device__ __forceinline__ float* buf_sel(int s) {
  switch (s) {
    case 0: return g_feat;
    case 1: return g_h1;
    case 2: return g_h2;
    case 3: return g_h3;
  }
  return 0;
}

// ---------------- fused KNN, d_in = 1 ----------------
__global__ __launch_bounds__(256) void knn1_kernel(const float* __restrict__ x) {
  int gw = (blockIdx.x << 3) + (threadIdx.x >> 5);
  int lane = threadIdx.x & 31;
  int b = gw >> 10;
  float xi = x[gw];
  const float* xb = x + (b << 10);
  float v[32];
#pragma unroll
  for (int q = 0; q < 32; q++) {
    float xj = xb[(q << 5) + lane];
    v[q] = xj * (xj - 2.0f * xi);
  }
  float bv = v[0]; int bq = 0;
#pragma unroll
  for (int q = 1; q < 32; q++) if (v[q] < bv) { bv = v[q]; bq = q; }
  int bidx = (bq << 5) + lane;
#pragma unroll 1
  for (int it = 0; it < 16; it++) {
    float wv = bv; int wi = bidx;
#pragma unroll
    for (int o = 16; o; o >>= 1) {
      float ov = __shfl_down_sync(0xffffffffu, wv, o);
      int   oi = __shfl_down_sync(0xffffffffu, wi, o);
      if (ov < wv || (ov == wv && oi < wi)) { wv = ov; wi = oi; }
    }
    wi = __shfl_sync(0xffffffffu, wi, 0);
    if (lane == 0) g_idx[(gw << 4) + it] = wi;
    if ((wi & 31) == lane) {
      int qr = wi >> 5;
#pragma unroll
      for (int q = 0; q < 32; q++) if (q == qr) v[q] = FINF;
      bv = v[0]; bq = 0;
#pragma unroll
      for (int q = 1; q < 32; q++) if (v[q] < bv) { bv = v[q]; bq = q; }
      bidx = (bq << 5) + lane;
    }
  }
}

// ---------------- KNN distance GEMM, d_in = 64 (FFMA2, symmetric) ----------------
// Upper-triangular 128x128 block pairs only: 36 blocks/batch instead of 64.
// Off-diagonal blocks write both (i,j) tile and transposed (j,i) tile.
__global__ __launch_bounds__(256, 2) void dist64_kernel(int featOff) {
  __shared__ float xiT[32][132];
  __shared__ float xjT[32][132];
  __shared__ float sqi[128];
  __shared__ float sqj[128];
  int tid = threadIdx.x;
  int b = blockIdx.y;

  // decode upper-triangular pair (by <= bx) from blockIdx.x in [0,36)
  int t = blockIdx.x, by = 0;
  while (t >= 8 - by) { t -= 8 - by; by++; }
  int bx = by + t;
  int i0 = by << 7;
  int j0 = bx << 7;
  const float* Xb = g_feat + ((size_t)b << 10) * 192 + featOff;

  int rb = tid & 15, cb = tid >> 4;
  int r0 = rb << 2, c0 = cb << 2;
  u64 acc2[8][4];
#pragma unroll
  for (int i = 0; i < 8; i++)
#pragma unroll
    for (int j = 0; j < 4; j++) acc2[i][j] = 0ULL;
  float sqa = 0.f, sqb = 0.f;

  for (int kc = 0; kc < 64; kc += 32) {
    __syncthreads();
#pragma unroll
    for (int tt = tid; tt < 1024; tt += 256) {
      int r = tt >> 3, dg = (tt & 7) << 2;
      float4 vi = *(const float4*)&Xb[(size_t)(i0 + r) * 192 + kc + dg];
      xiT[dg + 0][r] = vi.x; xiT[dg + 1][r] = vi.y;
      xiT[dg + 2][r] = vi.z; xiT[dg + 3][r] = vi.w;
      float4 vj = *(const float4*)&Xb[(size_t)(j0 + r) * 192 + kc + dg];
      xjT[dg + 0][r] = vj.x; xjT[dg + 1][r] = vj.y;
      xjT[dg + 2][r] = vj.z; xjT[dg + 3][r] = vj.w;
    }
    __syncthreads();
    if (tid < 128) {
#pragma unroll
      for (int d = 0; d < 32; d++) {
        float ui = xiT[d][tid]; sqa += ui * ui;
        float uj = xjT[d][tid]; sqb += uj * uj;
      }
    }
#pragma unroll
    for (int k = 0; k < 32; k++) {
      float a[8];
      *(float4*)&a[0] = *(const float4*)&xiT[k][r0];
      *(float4*)&a[4] = *(const float4*)&xiT[k][64 + r0];
      u64 bp[4];
      bp[0] = *(const u64*)&xjT[k][c0];
      bp[1] = *(const u64*)&xjT[k][c0 + 2];
      bp[2] = *(const u64*)&xjT[k][64 + c0];
      bp[3] = *(const u64*)&xjT[k][64 + c0 + 2];
#pragma unroll
      for (int i = 0; i < 8; i++) {
        u64 ad = pk2(a[i], a[i]);
#pragma unroll
        for (int jp = 0; jp < 4; jp++) fma2(acc2[i][jp], ad, bp[jp]);
      }
    }
  }
  if (tid < 128) { sqi[tid] = sqa; sqj[tid] = sqb; }
  __syncthreads();

  // unpack accumulators
  float accf[8][8];
#pragma unroll
  for (int i = 0; i < 8; i++)
#pragma unroll
    for (int jp = 0; jp < 4; jp++) {
      float2 p = up2(acc2[i][jp]);
      accf[i][2 * jp] = p.x; accf[i][2 * jp + 1] = p.y;
    }

  // tile (i0, j0): score = sqj[c] - 2*dot
#pragma unroll
  for (int i = 0; i < 8; i++) {
    int r = (i < 4) ? (r0 + i) : (64 + r0 + i - 4);
    float4 o0, o1;
    o0.x = sqj[c0 + 0] - 2.f * accf[i][0];
    o0.y = sqj[c0 + 1] - 2.f * accf[i][1];
    o0.z = sqj[c0 + 2] - 2.f * accf[i][2];
    o0.w = sqj[c0 + 3] - 2.f * accf[i][3];
    o1.x = sqj[64 + c0 + 0] - 2.f * accf[i][4];
    o1.y = sqj[64 + c0 + 1] - 2.f * accf[i][5];
    o1.z = sqj[64 + c0 + 2] - 2.f * accf[i][6];
    o1.w = sqj[64 + c0 + 3] - 2.f * accf[i][7];
    size_t base = (((size_t)(b << 10) + i0 + r) << 10) + j0;
    *(float4*)&g_dist[base + c0]      = o0;
    *(float4*)&g_dist[base + 64 + c0] = o1;
  }

  // tile (j0, i0) transposed: score = sqi[r] - 2*dot
  if (bx != by) {
#pragma unroll
    for (int j = 0; j < 8; j++) {
      int c = (j < 4) ? (c0 + j) : (64 + c0 + j - 4);
      float4 o0, o1;
      o0.x = sqi[r0 + 0] - 2.f * accf[0][j];
      o0.y = sqi[r0 + 1] - 2.f * accf[1][j];
      o0.z = sqi[r0 + 2] - 2.f * accf[2][j];
      o0.w = sqi[r0 + 3] - 2.f * accf[3][j];
      o1.x = sqi[64 + r0 + 0] - 2.f * accf[4][j];
      o1.y = sqi[64 + r0 + 1] - 2.f * accf[5][j];
      o1.z = sqi[64 + r0 + 2] - 2.f * accf[6][j];
      o1.w = sqi[64 + r0 + 3] - 2.f * accf[7][j];
      size_t base = (((size_t)(b << 10) + j0 + c) << 10) + i0;
      *(float4*)&g_dist[base + r0]      = o0;
      *(float4*)&g_dist[base + 64 + r0] = o1;
    }
  }
}

// ---------------- top-16: warp per row, register-resident ----------------
__global__ __launch_bounds__(256) void topk_kernel() {
  int gw = (blockIdx.x << 3) + (threadIdx.x >> 5);
  int lane = threadIdx.x & 31;
  const float* src = g_dist + ((size_t)gw << 10);
  float v[32];
#pragma unroll
  for (int q = 0; q < 32; q++) v[q] = src[(q << 5) + lane];
  float bv = v[0]; int bq = 0;
#pragma unroll
  for (int q = 1; q < 32; q++) if (v[q] < bv) { bv = v[q]; bq = q; }
  int bidx = (bq << 5) + lane;
#pragma unroll 1
  for (int it = 0; it < 16; it++) {
    float wv = bv; int wi = bidx;
#pragma unroll
    for (int o = 16; o; o >>= 1) {
      float ov = __shfl_down_sync(0xffffffffu, wv, o);
      int   oi = __shfl_down_sync(0xffffffffu, wi, o);
      if (ov < wv || (ov == wv && oi < wi)) { wv = ov; wi = oi; }
    }
    wi = __shfl_sync(0xffffffffu, wi, 0);
    if (lane == 0) g_idx[(gw << 4) + it] = wi;
    if ((wi & 31) == lane) {
      int qr = wi >> 5;
#pragma unroll
      for (int q = 0; q < 32; q++) if (q == qr) v[q] = FINF;
      bv = v[0]; bq = 0;
#pragma unroll
      for (int q = 1; q < 32; q++) if (v[q] < bv) { bv = v[q]; bq = q; }
      bidx = (bq << 5) + lane;
    }
  }
}

// ---------------- point-level A/P precompute ----------------
__global__ __launch_bounds__(256) void prec1_kernel(const float* __restrict__ x,
                                                    const float* __restrict__ w1,
                                                    const float* __restrict__ b1) {
  int t = blockIdx.x * 256 + threadIdx.x;
  int i = t >> 4;
  int c = (t & 15) << 2;
  float xi = x[i];
  float4 wa = *(const float4*)&w1[c];
  float4 wb = *(const float4*)&w1[64 + c];
  float4 bb = *(const float4*)&b1[c];
  float4 A, P;
  A.x = xi * (wa.x - wb.x) + bb.x;  P.x = xi * wb.x;
  A.y = xi * (wa.y - wb.y) + bb.y;  P.y = xi * wb.y;
  A.z = xi * (wa.z - wb.z) + bb.z;  P.z = xi * wb.z;
  A.w = xi * (wa.w - wb.w) + bb.w;  P.w = xi * wb.w;
  *(float4*)&g_A[(size_t)i * 64 + c] = A;
  *(float4*)&g_P[(size_t)i * 64 + c] = P;
}

__global__ __launch_bounds__(256) void prec64_kernel(int featOff,
                                                     const float* __restrict__ w1,
                                                     const float* __restrict__ b1) {
  __shared__ float xs[64][36];
  __shared__ float wd[32][64];
  __shared__ float wb[32][64];
  int tid = threadIdx.x;
  int row0 = blockIdx.x * 64;
  int rb = tid & 15, cb = tid >> 4;
  int r0 = rb * 4, c0 = cb * 4;
  float accA[4][4] = {}, accP[4][4] = {};

  for (int kc = 0; kc < 64; kc += 32) {
    __syncthreads();
    for (int t = tid; t < 2048; t += 256) {
      int rr = t >> 5, dd = t & 31;
      xs[rr][dd] = g_feat[(size_t)(row0 + rr) * 192 + featOff + kc + dd];
    }
    for (int t = tid; t < 2048; t += 256) {
      int kk = t >> 6, cc = t & 63;
      float bw = w1[(size_t)(64 + kc + kk) * 64 + cc];
      wb[kk][cc] = bw;
      wd[kk][cc] = w1[(size_t)(kc + kk) * 64 + cc] - bw;
    }
    __syncthreads();
#pragma unroll
    for (int k = 0; k < 32; k += 4) {
      float a[4][4];
#pragma unroll
      for (int i = 0; i < 4; i++) {
        float4 v = *(const float4*)&xs[r0 + i][k];
        a[i][0] = v.x; a[i][1] = v.y; a[i][2] = v.z; a[i][3] = v.w;
      }
#pragma unroll
      for (int kk = 0; kk < 4; kk++)
#pragma unroll
        for (int cc = 0; cc < 4; cc++) {
          float wdv = wd[k + kk][c0 + cc];
          float wbv = wb[k + kk][c0 + cc];
#pragma unroll
          for (int i = 0; i < 4; i++) {
            accA[i][cc] += a[i][kk] * wdv;
            accP[i][cc] += a[i][kk] * wbv;
          }
        }
    }
  }
#pragma unroll
  for (int i = 0; i < 4; i++)
#pragma unroll
    for (int cc = 0; cc < 4; cc++) {
      int r = row0 + r0 + i, c = c0 + cc;
      g_A[(size_t)r * 64 + c] = accA[i][cc] + b1[c];
      g_P[(size_t)r * 64 + c] = accP[i][cc];
    }
}

// ---------------- fused edge kernel (FFMA2 GEMM) ----------------
__global__ __launch_bounds__(128, 4) void edge_kernel(const float* __restrict__ w2,
                                                      const float* __restrict__ b2,
                                                      int outOff) {
  __shared__ float h1T[64][132];
  __shared__ float w2s[32][68];   // reused as red[32][68] after GEMM
  int tid = threadIdx.x;
  int p0 = blockIdx.x << 3;

  // build h1 rows transposed
  {
    int r = tid;
    int p = r >> 4, e = r & 15;
    int gi = p0 + p;
    int bb = gi >> 10;
    int j = g_idx[(gi << 4) + e];
    const float* Ar = g_A + ((size_t)gi << 6);
    const float* Pr = g_P + ((size_t)((bb << 10) + j) << 6);
#pragma unroll
    for (int d = 0; d < 64; d += 4) {
      float4 av = *(const float4*)(Ar + d);
      float4 pv = *(const float4*)(Pr + d);
      h1T[d + 0][r] = fmaxf(av.x + pv.x, 0.f);
      h1T[d + 1][r] = fmaxf(av.y + pv.y, 0.f);
      h1T[d + 2][r] = fmaxf(av.z + pv.z, 0.f);
      h1T[d + 3][r] = fmaxf(av.w + pv.w, 0.f);
    }
  }

  int rb = tid & 15, cb = tid >> 4;   // cb 0..7
  int r0 = rb << 2, c0 = cb << 2;
  u64 acc2[8][4];
#pragma unroll
  for (int i = 0; i < 8; i++)
#pragma unroll
    for (int j = 0; j < 4; j++) acc2[i][j] = 0ULL;

  for (int kc = 0; kc < 64; kc += 32) {
    __syncthreads();
    for (int t = tid; t < 512; t += 128) {
      int k = t >> 4, cg = (t & 15) << 2;
      *(float4*)&w2s[k][cg] = *(const float4*)&w2[((size_t)(kc + k) << 6) + cg];
    }
    __syncthreads();
#pragma unroll
    for (int k = 0; k < 32; k++) {
      float a[8];
      *(float4*)&a[0] = *(const float4*)&h1T[kc + k][r0];
      *(float4*)&a[4] = *(const float4*)&h1T[kc + k][64 + r0];
      u64 bp[4];
      bp[0] = *(const u64*)&w2s[k][c0];
      bp[1] = *(const u64*)&w2s[k][c0 + 2];
      bp[2] = *(const u64*)&w2s[k][32 + c0];
      bp[3] = *(const u64*)&w2s[k][32 + c0 + 2];
#pragma unroll
      for (int i = 0; i < 8; i++) {
        u64 ad = pk2(a[i], a[i]);
#pragma unroll
        for (int jp = 0; jp < 4; jp++) fma2(acc2[i][jp], ad, bp[jp]);
      }
    }
  }
  __syncthreads();               // all w2s reads done -> reuse as red
  float* red = &w2s[0][0];       // red[q][c] at red[q*68 + c], q 0..31

  // segmented max: rows r0..r0+3 -> point (rb>>2, slot rb&3); rows 64+r0.. -> point 4+(rb>>2)
#pragma unroll
  for (int jp = 0; jp < 4; jp++) {
    int c = (jp < 2) ? (c0 + 2 * jp) : (32 + c0 + 2 * (jp - 2));
    float2 v0 = up2(acc2[0][jp]);
    float2 v1 = up2(acc2[4][jp]);
    float m0x = v0.x, m0y = v0.y, m1x = v1.x, m1y = v1.y;
#pragma unroll
    for (int i = 1; i < 4; i++) {
      float2 a0 = up2(acc2[i][jp]);
      float2 a1 = up2(acc2[4 + i][jp]);
      m0x = fmaxf(m0x, a0.x); m0y = fmaxf(m0y, a0.y);
      m1x = fmaxf(m1x, a1.x); m1y = fmaxf(m1y, a1.y);
    }
    red[rb * 68 + c] = m0x;        red[rb * 68 + c + 1] = m0y;
    red[(16 + rb) * 68 + c] = m1x; red[(16 + rb) * 68 + c + 1] = m1y;
  }
  __syncthreads();

  // combine: point p partials live at red[4p + q], q=0..3
  {
    int p = tid >> 4;
    int c = (tid & 15) << 2;
    int base = 4 * p;
    float4 m = *(const float4*)&red[base * 68 + c];
#pragma unroll
    for (int q = 1; q < 4; q++) {
      float4 r4 = *(const float4*)&red[(base + q) * 68 + c];
      m.x = fmaxf(m.x, r4.x); m.y = fmaxf(m.y, r4.y);
      m.z = fmaxf(m.z, r4.z); m.w = fmaxf(m.w, r4.w);
    }
    float4 bb4 = *(const float4*)&b2[c];
    m.x += bb4.x; m.y += bb4.y; m.z += bb4.z; m.w += bb4.w;
    *(float4*)&g_feat[(size_t)(p0 + p) * 192 + outOff + c] = m;
  }
}

// ---------------- MLP1: 192 -> 128 (FFMA2 GEMM) ----------------
__global__ __launch_bounds__(256, 2) void mlp1_kernel(const float* __restrict__ W,
                                                      const float* __restrict__ bias) {
  __shared__ float xT[32][132];
  __shared__ float ws[32][132];
  int tid = threadIdx.x;
  int row0 = blockIdx.x << 7;
  int rb = tid & 15, cb = tid >> 4;
  int r0 = rb << 2, c0 = cb << 2;
  u64 acc2[8][4];
#pragma unroll
  for (int i = 0; i < 8; i++)
#pragma unroll
    for (int j = 0; j < 4; j++) acc2[i][j] = 0ULL;

  for (int kc = 0; kc < 192; kc += 32) {
    __syncthreads();
#pragma unroll
    for (int t = tid; t < 1024; t += 256) {
      int r = t >> 3, dg = (t & 7) << 2;
      float4 v = *(const float4*)&g_feat[(size_t)(row0 + r) * 192 + kc + dg];
      xT[dg + 0][r] = v.x; xT[dg + 1][r] = v.y;
      xT[dg + 2][r] = v.z; xT[dg + 3][r] = v.w;
    }
#pragma unroll
    for (int t = tid; t < 1024; t += 256) {
      int k = t >> 5, cg = (t & 31) << 2;
      *(float4*)&ws[k][cg] = *(const float4*)&W[(size_t)(kc + k) * 128 + cg];
    }
    __syncthreads();
#pragma unroll
    for (int k = 0; k < 32; k++) {
      float a[8];
      *(float4*)&a[0] = *(const float4*)&xT[k][r0];
      *(float4*)&a[4] = *(const float4*)&xT[k][64 + r0];
      u64 bp[4];
      bp[0] = *(const u64*)&ws[k][c0];
      bp[1] = *(const u64*)&ws[k][c0 + 2];
      bp[2] = *(const u64*)&ws[k][64 + c0];
      bp[3] = *(const u64*)&ws[k][64 + c0 + 2];
#pragma unroll
      for (int i = 0; i < 8; i++) {
        u64 ad = pk2(a[i], a[i]);
#pragma unroll
        for (int jp = 0; jp < 4; jp++) fma2(acc2[i][jp], ad, bp[jp]);
      }
    }
  }
#pragma unroll
  for (int i = 0; i < 8; i++) {
    int r = row0 + ((i < 4) ? (r0 + i) : (64 + r0 + i - 4));
    float2 p0 = up2(acc2[i][0]), p1 = up2(acc2[i][1]);
    float2 p2 = up2(acc2[i][2]), p3 = up2(acc2[i][3]);
    float4 o0, o1;
    o0.x = fmaxf(p0.x + bias[c0 + 0], 0.f);
    o0.y = fmaxf(p0.y + bias[c0 + 1], 0.f);
    o0.z = fmaxf(p1.x + bias[c0 + 2], 0.f);
    o0.w = fmaxf(p1.y + bias[c0 + 3], 0.f);
    o1.x = fmaxf(p2.x + bias[64 + c0 + 0], 0.f);
    o1.y = fmaxf(p2.y + bias[64 + c0 + 1], 0.f);
    o1.z = fmaxf(p3.x + bias[64 + c0 + 2], 0.f);
    o1.w = fmaxf(p3.y + bias[64 + c0 + 3], 0.f);
    *(float4*)&g_h1[((size_t)r << 7) + c0]      = o0;
    *(float4*)&g_h1[((size_t)r << 7) + 64 + c0] = o1;
  }
}

// ---------------- small MLP GEMMs ----------------
template <int K, int N, bool RELU>
__global__ __launch_bounds__(256) void gemm_kernel(int xsel, int sx,
                                                   const float* __restrict__ W,
                                                   const float* __restrict__ bias,
                                                   int osel, int so) {
  constexpr int CT = N / 16;
  __shared__ float xs[64][36];
  __shared__ float ws[32][N];
  const float* X = buf_sel(xsel);
  float* out = buf_sel(osel);
  int tid = threadIdx.x;
  int row0 = blockIdx.x * 64;
  int rb = tid & 15, cb = tid >> 4;
  int r0 = rb * 4, c0 = cb * CT;
  float acc[4][CT];
#pragma unroll
  for (int i = 0; i < 4; i++)
#pragma unroll
    for (int c = 0; c < CT; c++) acc[i][c] = 0.f;

  for (int kc = 0; kc < K; kc += 32) {
    __syncthreads();
    for (int t = tid; t < 2048; t += 256) {
      int rr = t >> 5, dd = t & 31;
      xs[rr][dd] = X[(size_t)(row0 + rr) * sx + kc + dd];
    }
    for (int t = tid; t < 32 * N; t += 256) {
      int kk = t / N, cc = t % N;
      ws[kk][cc] = W[(size_t)(kc + kk) * N + cc];
    }
    __syncthreads();
#pragma unroll
    for (int k = 0; k < 32; k += 4) {
      float a[4][4];
#pragma unroll
      for (int i = 0; i < 4; i++) {
        float4 v = *(const float4*)&xs[r0 + i][k];
        a[i][0] = v.x; a[i][1] = v.y; a[i][2] = v.z; a[i][3] = v.w;
      }
#pragma unroll
      for (int kk = 0; kk < 4; kk++)
#pragma unroll
        for (int cc = 0; cc < CT; cc++) {
          float wv = ws[k + kk][c0 + cc];
#pragma unroll
          for (int i = 0; i < 4; i++) acc[i][cc] += a[i][kk] * wv;
        }
    }
  }
#pragma unroll
  for (int i = 0; i < 4; i++)
#pragma unroll
    for (int cc = 0; cc < CT; cc++) {
      float v = acc[i][cc] + bias[c0 + cc];
      if (RELU) v = fmaxf(v, 0.f);
      out[(size_t)(row0 + r0 + i) * so + c0 + cc] = v;
    }
}

// ---------------- final layer (32 -> 2) + log_softmax ----------------
__global__ __launch_bounds__(256) void final_kernel(const float* __restrict__ w4,
                                                    const float* __restrict__ b4,
                                                    float* __restrict__ out) {
  int i = blockIdx.x * 256 + threadIdx.x;
  const float* h = g_h3 + (size_t)i * 32;
  float z0 = b4[0], z1 = b4[1];
#pragma unroll
  for (int k = 0; k < 32; k += 4) {
    float4 v = *(const float4*)&h[k];
    z0 += v.x * w4[(k + 0) * 2 + 0];  z1 += v.x * w4[(k + 0) * 2 + 1];
    z0 += v.y * w4[(k + 1) * 2 + 0];  z1 += v.y * w4[(k + 1) * 2 + 1];
    z0 += v.z * w4[(k + 2) * 2 + 0];  z1 += v.z * w4[(k + 2) * 2 + 1];
    z0 += v.w * w4[(k + 3) * 2 + 0];  z1 += v.w * w4[(k + 3) * 2 + 1];
  }
  float m = fmaxf(z0, z1);
  float l = m + logf(expf(z0 - m) + expf(z1 - m));
  out[2 * i + 0] = z0 - l;
  out[2 * i + 1] = z1 - l;
}

// ---------------- launch ----------------
extern "C" void kernel_launch(void* const* d_in, const int* in_sizes, int n_in,
                              void* d_out, int out_size) {
  const float* x    = (const float*)d_in[0];
  const float* c1w1 = (const float*)d_in[1];
  const float* c1b1 = (const float*)d_in[2];
  const float* c1w2 = (const float*)d_in[3];
  const float* c1b2 = (const float*)d_in[4];
  const float* c2w1 = (const float*)d_in[5];
  const float* c2b1 = (const float*)d_in[6];
  const float* c2w2 = (const float*)d_in[7];
  const float* c2b2 = (const float*)d_in[8];
  const float* c3w1 = (const float*)d_in[9];
  const float* c3b1 = (const float*)d_in[10];
  const float* c3w2 = (const float*)d_in[11];
  const float* c3b2 = (const float*)d_in[12];
  const float* mw1  = (const float*)d_in[13];
  const float* mb1  = (const float*)d_in[14];
  const float* mw2  = (const float*)d_in[15];
  const float* mb2  = (const float*)d_in[16];
  const float* mw3  = (const float*)d_in[17];
  const float* mb3  = (const float*)d_in[18];
  const float* mw4  = (const float*)d_in[19];
  const float* mb4  = (const float*)d_in[20];
  float* out = (float*)d_out;

  // ---- EdgeConv 1 (d_in = 1) ----
  knn1_kernel<<<8192, 256>>>(x);
  prec1_kernel<<<4096, 256>>>(x, c1w1, c1b1);
  edge_kernel<<<8192, 128>>>(c1w2, c1b2, 0);

  // ---- EdgeConv 2 (on x1, d_in = 64) ----
  dist64_kernel<<<dim3(36, 64), 256>>>(0);
  topk_kernel<<<8192, 256>>>();
  prec64_kernel<<<1024, 256>>>(0, c2w1, c2b1);
  edge_kernel<<<8192, 128>>>(c2w2, c2b2, 64);

  // ---- EdgeConv 3 (on x2, d_in = 64) ----
  dist64_kernel<<<dim3(36, 64), 256>>>(64);
  topk_kernel<<<8192, 256>>>();
  prec64_kernel<<<1024, 256>>>(64, c3w1, c3b1);
  edge_kernel<<<8192, 128>>>(c3w2, c3b2, 128);

  // ---- MLP head ----
  mlp1_kernel<<<512, 256>>>(mw1, mb1);
  gemm_kernel<128, 64, true><<<1024, 256>>>(1, 128, mw2, mb2, 2, 64);
  gemm_kernel<64, 32, true><<<1024, 256>>>(2, 64, mw3, mb3, 3, 32);
  final_kernel<<<256, 256>>>(mw4, mb4, out);
}